// round 3
// baseline (speedup 1.0000x reference)
#include <cuda_runtime.h>
#include <math.h>

#define B      32
#define TIN    256
#define TOUT   512
#define NMEL   80
#define NBLK   128
#define NTHR   512

#define GATE_OFF  (B*NMEL*TOUT)
#define ALIGN_OFF (GATE_OFF + B*TOUT)

typedef unsigned long long ull;

// ---------------------------------------------------------------------------
// packed fp32x2 helpers (Blackwell FFMA2 — PTX only)
// ---------------------------------------------------------------------------
__device__ __forceinline__ void fma2(ull &d, ull a, ull b) {
    asm("fma.rn.f32x2 %0, %1, %2, %3;" : "=l"(d) : "l"(a), "l"(b), "l"(d));
}
__device__ __forceinline__ float hsum(ull v) {
    float a, b;
    asm("mov.b64 {%0,%1}, %2;" : "=f"(a), "=f"(b) : "l"(v));
    return a + b;
}
__device__ __forceinline__ float fsig(float x)  { return __fdividef(1.f, 1.f + __expf(-x)); }
__device__ __forceinline__ float ftanh(float x) { return 1.f - __fdividef(2.f, __expf(2.f * x) + 1.f); }

// ---------------------------------------------------------------------------
// device-global state. Activation packing: float index for feature k, batch b
// is  (k>>2)*4*B + b*4 + (k&3)  -> as ulonglong2 (16B):  (k>>2)*B + b.
// ---------------------------------------------------------------------------
__device__ __align__(16) float g_P[TOUT * 256 * B];     // prenet out, packed, slab 8192/t
__device__ __align__(16) float g_pm[B * TIN * 128];     // processed_memory
__device__ __align__(16) float g_memT[B * 512 * TIN];   // memory transposed [b][e][t]
__device__ __align__(16) float g_ctx[512 * B];          // context, packed
__device__ __align__(16) float g_ah[2][1024 * B];       // att h ping-pong, packed
__device__ __align__(16) float g_ac[1024 * B];
__device__ __align__(16) float g_dh[2][1024 * B];       // dec h ping-pong, packed
__device__ __align__(16) float g_dc[1024 * B];
__device__ float g_aw[B * TIN];
__device__ float g_awc[B * TIN];
__device__ float g_e[B * TIN];
__device__ float g_pq[B * 128];
__device__ volatile unsigned g_gen;
__device__ unsigned g_cnt;

// ---------------------------------------------------------------------------
// grid barrier (generation counter; reset kernel zeroes g_gen/g_cnt so graph
// replays start consistent). All 128 CTAs are co-resident (128 <= 148 SMs,
// 1 CTA/SM).
// ---------------------------------------------------------------------------
__device__ __forceinline__ void gbar(unsigned &gen) {
    gen++;
    __threadfence();
    __syncthreads();
    if (threadIdx.x == 0) {
        if (atomicAdd(&g_cnt, 1u) == NBLK - 1) {
            g_cnt = 0;
            __threadfence();
            g_gen = gen;
        } else {
            while (g_gen < gen) { }
        }
    }
    __syncthreads();
}

__global__ void k_reset() { g_gen = 0; g_cnt = 0; }

// ---------------------------------------------------------------------------
// vectorized dot helpers: per iter 5x LDG.128 + 8 packed fma
// ---------------------------------------------------------------------------
__device__ __forceinline__ void dot4(ull &a0, ull &a1, ull &a2, ull &a3,
    const ulonglong2* __restrict__ w0, const ulonglong2* __restrict__ w1,
    const ulonglong2* __restrict__ w2, const ulonglong2* __restrict__ w3,
    const ulonglong2* __restrict__ x, int n, int lane) {
#pragma unroll 2
    for (int i = 0; i < n; i++) {
        ulonglong2 xv = x[i * B + lane];
        ulonglong2 p0 = w0[i], p1 = w1[i], p2 = w2[i], p3 = w3[i];
        fma2(a0, p0.x, xv.x); fma2(a0, p0.y, xv.y);
        fma2(a1, p1.x, xv.x); fma2(a1, p1.y, xv.y);
        fma2(a2, p2.x, xv.x); fma2(a2, p2.y, xv.y);
        fma2(a3, p3.x, xv.x); fma2(a3, p3.y, xv.y);
    }
}

__device__ __forceinline__ void dot1(ull &a,
    const ulonglong2* __restrict__ w, const ulonglong2* __restrict__ x,
    int n, int lane) {
#pragma unroll 2
    for (int i = 0; i < n; i++) {
        ulonglong2 xv = x[i * B + lane];
        ulonglong2 wv = w[i];
        fma2(a, wv.x, xv.x); fma2(a, wv.y, xv.y);
    }
}

// ---------------------------------------------------------------------------
// LSTM phase: group u (4 gate rows) computed by 2 warps (K-split), smem reduce.
// Virtual K (in 16B q-units): segA (LAQ) | ctx (128) | h (256)
// ---------------------------------------------------------------------------
template<int LAQ>
__device__ __forceinline__ void lstm_phase(
    const float* __restrict__ wih, const float* __restrict__ whh,
    const float* __restrict__ bias,
    const float* __restrict__ xA, const float* __restrict__ ctx,
    const float* __restrict__ hprev,
    float* __restrict__ cst, float* __restrict__ hout,
    int cta, int wi, int lane, float* s_red) {
    __syncthreads();   // protect s_red reuse vs previous phase
    const int RSQ = LAQ + 128;     // ih row stride in q-units
    const int TOT = LAQ + 128 + 256;
    const int HALF = TOT / 2;
    int g = wi >> 1, ks = wi & 1;
    int u = cta * 8 + g;
    const ulonglong2* Wih = (const ulonglong2*)wih;
    const ulonglong2* Whh = (const ulonglong2*)whh;
    const ulonglong2* XA  = (const ulonglong2*)xA;
    const ulonglong2* XC  = (const ulonglong2*)ctx;
    const ulonglong2* XH  = (const ulonglong2*)hprev;
    int k0 = ks * HALF, k1 = k0 + HALF;
    ull a0 = 0, a1 = 0, a2 = 0, a3 = 0;
    {   // seg A
        int lo = k0, hi = (k1 < LAQ) ? k1 : LAQ, n = hi - lo;
        if (n > 0)
            dot4(a0, a1, a2, a3,
                 Wih + (size_t)u * RSQ + lo,
                 Wih + (size_t)(u + 1024) * RSQ + lo,
                 Wih + (size_t)(u + 2048) * RSQ + lo,
                 Wih + (size_t)(u + 3072) * RSQ + lo,
                 XA + (size_t)lo * B, n, lane);
    }
    {   // seg B (ctx)
        int lo = (k0 > LAQ) ? k0 : LAQ;
        int hi = (k1 < LAQ + 128) ? k1 : (LAQ + 128);
        int n = hi - lo;
        if (n > 0)
            dot4(a0, a1, a2, a3,
                 Wih + (size_t)u * RSQ + lo,
                 Wih + (size_t)(u + 1024) * RSQ + lo,
                 Wih + (size_t)(u + 2048) * RSQ + lo,
                 Wih + (size_t)(u + 3072) * RSQ + lo,
                 XC + (size_t)(lo - LAQ) * B, n, lane);
    }
    {   // seg C (h)
        int lo = (k0 > LAQ + 128) ? k0 : (LAQ + 128);
        int hi = k1, n = hi - lo;
        if (n > 0) {
            int c = lo - (LAQ + 128);
            dot4(a0, a1, a2, a3,
                 Whh + (size_t)u * 256 + c,
                 Whh + (size_t)(u + 1024) * 256 + c,
                 Whh + (size_t)(u + 2048) * 256 + c,
                 Whh + (size_t)(u + 3072) * 256 + c,
                 XH + (size_t)c * B, n, lane);
        }
    }
    int base = ((g * 2 + ks) * 4) * 32 + lane;
    s_red[base]      = hsum(a0);
    s_red[base + 32] = hsum(a1);
    s_red[base + 64] = hsum(a2);
    s_red[base + 96] = hsum(a3);
    __syncthreads();
    if (ks == 0) {
        int b0 = ((g * 2 + 0) * 4) * 32 + lane;
        int b1 = ((g * 2 + 1) * 4) * 32 + lane;
        float gi = s_red[b0]      + s_red[b1]      + bias[u];
        float gf = s_red[b0 + 32] + s_red[b1 + 32] + bias[u + 1024];
        float gg = s_red[b0 + 64] + s_red[b1 + 64] + bias[u + 2048];
        float go = s_red[b0 + 96] + s_red[b1 + 96] + bias[u + 3072];
        float c  = cst[u * 32 + lane];
        float c2 = fsig(gf) * c + fsig(gi) * ftanh(gg);
        float h2 = fsig(go) * ftanh(c2);
        cst[u * 32 + lane] = c2;
        hout[(u >> 2) * 128 + lane * 4 + (u & 3)] = h2;
    }
}

// ---------------------------------------------------------------------------
// the persistent kernel
// ---------------------------------------------------------------------------
__global__ void __launch_bounds__(NTHR, 1) k_main(
    const float* __restrict__ memory, const float* __restrict__ dec_in,
    const int*   __restrict__ memlen,
    const float* __restrict__ prenet_w1, const float* __restrict__ prenet_w2,
    const float* __restrict__ att_wih, const float* __restrict__ att_whh,
    const float* __restrict__ att_b,
    const float* __restrict__ wq, const float* __restrict__ wm,
    const float* __restrict__ v,
    const float* __restrict__ loc_conv, const float* __restrict__ loc_dense,
    const float* __restrict__ dec_wih, const float* __restrict__ dec_whh,
    const float* __restrict__ dec_b,
    const float* __restrict__ proj_w, const float* __restrict__ proj_b,
    const float* __restrict__ gate_w, const float* __restrict__ gate_b,
    float* __restrict__ out) {

    __shared__ float s_lc[1984];      // loc_conv
    __shared__ float s_dense[4096];   // loc_dense
    __shared__ float s_v[128];
    __shared__ float s_scr[3328];     // union scratch (lstm reduce / energy / prenet / prep / softmax)

    const int cta = blockIdx.x;
    const int tid = threadIdx.x;
    const int wi = tid >> 5, lane = tid & 31;
    unsigned gen = 0;

    // ---- constants to smem ----
    for (int i = tid; i < 1984; i += NTHR) s_lc[i] = loc_conv[i];
    for (int i = tid; i < 4096; i += NTHR) s_dense[i] = loc_dense[i];
    if (tid < 128) s_v[tid] = v[tid];

    // ---- zero recurrent state ----
    for (int i = cta * NTHR + tid; i < 1024 * B; i += NBLK * NTHR) {
        g_ac[i] = 0.f; g_dc[i] = 0.f;
        g_ah[0][i] = 0.f; g_ah[1][i] = 0.f;
        g_dh[0][i] = 0.f; g_dh[1][i] = 0.f;
    }
    for (int i = cta * NTHR + tid; i < 512 * B; i += NBLK * NTHR) g_ctx[i] = 0.f;
    for (int i = cta * NTHR + tid; i < B * TIN; i += NBLK * NTHR) { g_aw[i] = 0.f; g_awc[i] = 0.f; }

    // ---- prenet for all 512 steps (64 rounds x 2 groups of 256 threads) ----
    {
        int grp = tid >> 8, sub = tid & 255;
        float* sd = s_scr + grp * 512;
        float* sx = sd + 96;
        for (int r = 0; r < 64; r++) {
            int job = r * 256 + cta * 2 + grp;
            int t = job >> 5, b = job & 31;
            __syncthreads();
            if (sub < 80)
                sd[sub] = (t == 0) ? 0.f : dec_in[(size_t)b * NMEL * TOUT + sub * TOUT + (t - 1)];
            __syncthreads();
            float s = 0.f;
            const float* w = prenet_w1 + sub * 80;
#pragma unroll 8
            for (int m = 0; m < 80; m++) s += w[m] * sd[m];
            sx[sub] = fmaxf(s, 0.f);
            __syncthreads();
            s = 0.f;
            const float* w2 = prenet_w2 + sub * 256;
#pragma unroll 8
            for (int m = 0; m < 256; m++) s += w2[m] * sx[m];
            s = fmaxf(s, 0.f);
            g_P[(size_t)t * 8192 + (sub >> 2) * 128 + b * 4 + (sub & 3)] = s;
        }
    }

    // ---- processed_memory + memory transpose (16 rounds x 4 groups of 128) ----
    {
        int grp = tid >> 7, sub = tid & 127;
        float* sm = s_scr + grp * 512;
        for (int r = 0; r < 16; r++) {
            int job = r * 512 + cta * 4 + grp;
            int tt = job >> 5, b = job & 31;
            __syncthreads();
            for (int e = sub; e < 512; e += 128) {
                float vv = memory[((size_t)b * TIN + tt) * 512 + e];
                sm[e] = vv;
                g_memT[((size_t)b * 512 + e) * TIN + tt] = vv;
            }
            __syncthreads();
            float s = 0.f;
            const float* w = wm + sub * 512;
#pragma unroll 8
            for (int e = 0; e < 512; e++) s += w[e] * sm[e];
            g_pm[((size_t)b * TIN + tt) * 128 + sub] = s;
        }
    }

    gbar(gen);

    // ======================= main recurrence =======================
    for (int t = 0; t < TOUT; t++) {
        int p = t & 1;

        // ---- P1: attention LSTM ----
        lstm_phase<64>(att_wih, att_whh, att_b,
                       g_P + (size_t)t * 8192, g_ctx, g_ah[p],
                       g_ac, g_ah[p ^ 1], cta, wi, lane, s_scr);
        gbar(gen);

        // ---- P2: pq = ah @ wq^T (CTAs 0..15) ----
        __syncthreads();
        {
            int g = wi >> 1, ks = wi & 1;
            if (cta < 16) {
                int a = cta * 8 + g;
                ull acc = 0;
                dot1(acc, (const ulonglong2*)wq + (size_t)a * 256 + ks * 128,
                     (const ulonglong2*)g_ah[p ^ 1] + (size_t)ks * 128 * B, 128, lane);
                s_scr[(g * 2 + ks) * 32 + lane] = hsum(acc);
            }
            __syncthreads();
            if (cta < 16 && ks == 0) {
                int a = cta * 8 + g;
                g_pq[lane * 128 + a] = s_scr[(g * 2) * 32 + lane] + s_scr[(g * 2 + 1) * 32 + lane];
            }
        }
        gbar(gen);

        // ---- P3: energies (2 tiles per CTA, 256 threads each) ----
        {
            int ts = tid >> 8, sub = tid & 255;
            int tile = cta * 2 + ts;            // 0..255 = 8 t-tiles x 32 b
            int b = tile >> 3;
            int t0 = (tile & 7) * 32;
            float* scr  = s_scr + ts * 1600;
            float* cat  = scr;                  // [2][64]
            float* co   = scr + 128;            // [32][33]
            float* spq  = scr + 1184;           // [128]
            float* part = scr + 1312;           // [256]
            if (sub < 124) {
                int c = sub / 62, tl = sub % 62;
                int tg = t0 - 15 + tl;
                float vv = 0.f;
                if (tg >= 0 && tg < TIN) vv = (c ? g_awc : g_aw)[b * TIN + tg];
                cat[c * 64 + tl] = vv;
            }
            if (sub < 128) spq[sub] = g_pq[b * 128 + sub];
            __syncthreads();
#pragma unroll
            for (int j = 0; j < 4; j++) {
                int id = sub + j * 256;
                int tl = id >> 5, f = id & 31;
                const float* lc = &s_lc[f * 62];
                float s = 0.f;
#pragma unroll
                for (int k = 0; k < 31; k++) s += lc[k] * cat[tl + k];
#pragma unroll
                for (int k = 0; k < 31; k++) s += lc[31 + k] * cat[64 + tl + k];
                co[tl * 33 + f] = s;
            }
            __syncthreads();
            {
                int tl = sub >> 3, a0i = (sub & 7) * 16;
                const float* pmrow = g_pm + ((size_t)(b * TIN + t0 + tl)) * 128;
                float acc = 0.f;
#pragma unroll 2
                for (int a = a0i; a < a0i + 16; a++) {
                    const float* dw = &s_dense[a * 32];
                    float loc = 0.f;
#pragma unroll
                    for (int f = 0; f < 32; f++) loc += dw[f] * co[tl * 33 + f];
                    acc += ftanh(spq[a] + pmrow[a] + loc) * s_v[a];
                }
                part[tl * 8 + (sub & 7)] = acc;
            }
            __syncthreads();
            if (sub < 32) {
                float e = 0.f;
#pragma unroll
                for (int j = 0; j < 8; j++) e += part[sub * 8 + j];
                int tg = t0 + sub;
                if (tg >= memlen[b]) e = -1e9f;
                g_e[b * TIN + tg] = e;
            }
        }
        gbar(gen);

        // ---- P4: softmax + context (CTA -> (b, e-quarter)) ----
        {
            int b = cta >> 2, x = cta & 3;
            float* s_w  = s_scr;
            float* red  = s_scr + 256;
            float* bval = s_scr + 266;
            float e = (tid < 256) ? g_e[b * 256 + tid] : -1e30f;
            float m = e;
#pragma unroll
            for (int o = 16; o; o >>= 1) m = fmaxf(m, __shfl_xor_sync(0xffffffffu, m, o));
            if (lane == 0 && tid < 256) red[wi] = m;
            __syncthreads();
            if (tid == 0) {
                float mm = red[0];
#pragma unroll
                for (int i = 1; i < 8; i++) mm = fmaxf(mm, red[i]);
                bval[0] = mm;
            }
            __syncthreads();
            float w0 = (tid < 256) ? __expf(e - bval[0]) : 0.f;
            float ssum = w0;
#pragma unroll
            for (int o = 16; o; o >>= 1) ssum += __shfl_xor_sync(0xffffffffu, ssum, o);
            if (lane == 0 && tid < 256) red[wi] = ssum;
            __syncthreads();
            if (tid == 0) {
                float tt2 = 0.f;
#pragma unroll
                for (int i = 0; i < 8; i++) tt2 += red[i];
                bval[1] = tt2;
            }
            __syncthreads();
            if (tid < 256) {
                float wgt = w0 * __fdividef(1.f, bval[1]);
                s_w[tid] = wgt;
                if (x == 0) {
                    g_aw[b * 256 + tid] = wgt;
                    g_awc[b * 256 + tid] += wgt;
                    out[ALIGN_OFF + (size_t)(b * TOUT + t) * TIN + tid] = wgt;
                }
            }
            __syncthreads();
            if (tid < 256) {
                int ebase = x * 128 + wi * 16;
#pragma unroll 2
                for (int i = 0; i < 16; i++) {
                    int e2 = ebase + i;
                    const float* mrow = g_memT + ((size_t)b * 512 + e2) * TIN;
                    float s = 0.f;
#pragma unroll
                    for (int j = 0; j < 8; j++) {
                        int tt3 = lane + 32 * j;
                        s += mrow[tt3] * s_w[tt3];
                    }
#pragma unroll
                    for (int o = 16; o; o >>= 1) s += __shfl_down_sync(0xffffffffu, s, o);
                    if (lane == 0)
                        g_ctx[(e2 >> 2) * 128 + b * 4 + (e2 & 3)] = s;
                }
            }
        }
        gbar(gen);

        // ---- P5: decoder LSTM ----
        lstm_phase<256>(dec_wih, dec_whh, dec_b,
                        g_ah[p ^ 1], g_ctx, g_dh[p],
                        g_dc, g_dh[p ^ 1], cta, wi, lane, s_scr);
        gbar(gen);

        // ---- P6: projection + gate (CTAs 0..10; no trailing barrier) ----
        __syncthreads();
        {
            int g = wi >> 1, ks = wi & 1;
            int o = cta * 8 + g;
            if (cta < 11 && o < 81) {
                const ulonglong2* W = (o < 80) ? ((const ulonglong2*)proj_w + (size_t)o * 384)
                                               : (const ulonglong2*)gate_w;
                const ulonglong2* XD = (const ulonglong2*)g_dh[p ^ 1];
                const ulonglong2* XC = (const ulonglong2*)g_ctx;
                int k0 = ks * 192, k1 = k0 + 192;
                ull acc = 0;
                {
                    int lo = k0, hi = (k1 < 256) ? k1 : 256, n = hi - lo;
                    if (n > 0) dot1(acc, W + lo, XD + (size_t)lo * B, n, lane);
                }
                {
                    int lo = (k0 > 256) ? k0 : 256, hi = k1, n = hi - lo;
                    if (n > 0) dot1(acc, W + lo, XC + (size_t)(lo - 256) * B, n, lane);
                }
                s_scr[(g * 2 + ks) * 32 + lane] = hsum(acc);
            }
            __syncthreads();
            if (cta < 11 && o < 81 && ks == 0) {
                float s = s_scr[(g * 2) * 32 + lane] + s_scr[(g * 2 + 1) * 32 + lane]
                        + ((o < 80) ? proj_b[o] : gate_b[0]);
                if (o < 80)
                    out[(size_t)(lane * NMEL + o) * TOUT + t] = s;
                else
                    out[GATE_OFF + (size_t)lane * TOUT + t] = s;
            }
        }
    }
}

// ---------------------------------------------------------------------------
// launch: 2 graph nodes total
// ---------------------------------------------------------------------------
extern "C" void kernel_launch(void* const* d_in, const int* in_sizes, int n_in,
                              void* d_out, int out_size) {
    const float* memory    = (const float*)d_in[0];
    const float* dec_in    = (const float*)d_in[1];
    const int*   memlen    = (const int*)  d_in[2];
    const float* prenet_w1 = (const float*)d_in[3];
    const float* prenet_w2 = (const float*)d_in[4];
    const float* att_wih   = (const float*)d_in[5];
    const float* att_whh   = (const float*)d_in[6];
    const float* att_b     = (const float*)d_in[7];
    const float* wq        = (const float*)d_in[8];
    const float* wm        = (const float*)d_in[9];
    const float* v         = (const float*)d_in[10];
    const float* loc_conv  = (const float*)d_in[11];
    const float* loc_dense = (const float*)d_in[12];
    const float* dec_wih   = (const float*)d_in[13];
    const float* dec_whh   = (const float*)d_in[14];
    const float* dec_b     = (const float*)d_in[15];
    const float* proj_w    = (const float*)d_in[16];
    const float* proj_b    = (const float*)d_in[17];
    const float* gate_w    = (const float*)d_in[18];
    const float* gate_b    = (const float*)d_in[19];
    float* out = (float*)d_out;

    k_reset<<<1, 32>>>();
    k_main<<<NBLK, NTHR>>>(memory, dec_in, memlen, prenet_w1, prenet_w2,
                           att_wih, att_whh, att_b, wq, wm, v,
                           loc_conv, loc_dense, dec_wih, dec_whh, dec_b,
                           proj_w, proj_b, gate_w, gate_b, out);
}

// round 4
// speedup vs baseline: 1.1458x; 1.1458x over previous
#include <cuda_runtime.h>
#include <math.h>

#define B      32
#define TIN    256
#define TOUT   512
#define NMEL   80
#define NBLK   128
#define NTHR   512

#define GATE_OFF  (B*NMEL*TOUT)
#define ALIGN_OFF (GATE_OFF + B*TOUT)

typedef unsigned long long ull;

// ---------------------------------------------------------------------------
// packed fp32x2 helpers (Blackwell FFMA2 — PTX only)
// ---------------------------------------------------------------------------
__device__ __forceinline__ void fma2(ull &d, ull a, ull b) {
    asm("fma.rn.f32x2 %0, %1, %2, %3;" : "=l"(d) : "l"(a), "l"(b), "l"(d));
}
__device__ __forceinline__ float hsum(ull v) {
    float a, b;
    asm("mov.b64 {%0,%1}, %2;" : "=f"(a), "=f"(b) : "l"(v));
    return a + b;
}
__device__ __forceinline__ float fsig(float x)  { return __fdividef(1.f, 1.f + __expf(-x)); }
__device__ __forceinline__ float ftanh(float x) { return 1.f - __fdividef(2.f, __expf(2.f * x) + 1.f); }

// ---------------------------------------------------------------------------
// device-global state. Activation packing: float index for feature k, batch b
// is  (k>>2)*4*B + b*4 + (k&3)  -> as ulonglong2 (16B):  (k>>2)*B + b.
// ---------------------------------------------------------------------------
__device__ __align__(16) float g_P[TOUT * 256 * B];     // prenet out, packed, slab 8192/t
__device__ __align__(16) float g_pm[B * TIN * 128];     // processed_memory
__device__ __align__(16) float g_memT[B * 512 * TIN];   // memory transposed [b][e][t]
__device__ __align__(16) float g_ctx[512 * B];          // context, packed
__device__ __align__(16) float g_ah[2][1024 * B];       // att h ping-pong, packed
__device__ __align__(16) float g_ac[1024 * B];
__device__ __align__(16) float g_dh[2][1024 * B];       // dec h ping-pong, packed
__device__ __align__(16) float g_dc[1024 * B];
__device__ float g_aw[B * TIN];
__device__ float g_awc[B * TIN];
__device__ float g_e[B * TIN];
__device__ float g_pq[B * 128];
__device__ volatile unsigned g_gen;
__device__ unsigned g_cnt;

// ---------------------------------------------------------------------------
// grid barrier (all 128 CTAs co-resident, 1/SM)
// ---------------------------------------------------------------------------
__device__ __forceinline__ void gbar(unsigned &gen) {
    gen++;
    __threadfence();
    __syncthreads();
    if (threadIdx.x == 0) {
        if (atomicAdd(&g_cnt, 1u) == NBLK - 1) {
            g_cnt = 0;
            __threadfence();
            g_gen = gen;
        } else {
            while (g_gen < gen) { }
        }
    }
    __syncthreads();
}

__global__ void k_reset() { g_gen = 0; g_cnt = 0; }

// ---------------------------------------------------------------------------
// small dot helper for pq / proj (unchanged, weights streamed via LDG)
// ---------------------------------------------------------------------------
__device__ __forceinline__ void dot1(ull &a,
    const ulonglong2* __restrict__ w, const ulonglong2* __restrict__ x,
    int n, int lane) {
#pragma unroll 2
    for (int i = 0; i < n; i++) {
        ulonglong2 xv = x[i * B + lane];
        ulonglong2 wv = w[i];
        fma2(a, wv.x, xv.x); fma2(a, wv.y, xv.y);
    }
}

// ---------------------------------------------------------------------------
// cp.async helpers
// ---------------------------------------------------------------------------
__device__ __forceinline__ void cp16(unsigned dst, const void* src) {
    asm volatile("cp.async.cg.shared.global [%0], [%1], 16;" :: "r"(dst), "l"(src) : "memory");
}
__device__ __forceinline__ void cp_commit() {
    asm volatile("cp.async.commit_group;" ::: "memory");
}
__device__ __forceinline__ void cp_wait1() {
    asm volatile("cp.async.wait_group 1;" ::: "memory");
}
__device__ __forceinline__ void cp_wait0() {
    asm volatile("cp.async.wait_group 0;" ::: "memory");
}

// ---------------------------------------------------------------------------
// LSTM phase, smem-pipelined.
// CTA owns u-groups cta*8..cta*8+7 -> 32 gate rows (tile row = gate*8 + g).
// K processed in stages of 16 q-units (16B each). Weight tile per stage:
// 32 rows x 64 floats = 8KB, double buffered in s_u[0..4095].
// s_red = s_u + 4096 (2048 floats).
// warp (g = wi>>1, ks = wi&1) computes group g's 4 gate rows over its
// half (8 kq) of each stage; x via LDG (L1-resident), weights via uniform LDS.
// ---------------------------------------------------------------------------
template<int LAQ>
__device__ __forceinline__ void lstm_phase(
    const float* __restrict__ wih, const float* __restrict__ whh,
    const float* __restrict__ bias,
    const float* __restrict__ xA, const float* __restrict__ ctx,
    const float* __restrict__ hprev,
    float* __restrict__ cst, float* __restrict__ hout,
    int cta, int wi, int lane, int tid, float* s_u) {

    const int RSQ = LAQ + 128;          // wih row stride, q-units
    const int KQ  = LAQ + 128 + 256;    // total K, q-units
    const int NST = KQ / 16;

    float* w_s   = s_u;                 // [2][32][64] floats
    float* s_red = s_u + 4096;

    __syncthreads();                    // protect s_u reuse vs previous phase

    const ulonglong2* Wih = (const ulonglong2*)wih;
    const ulonglong2* Whh = (const ulonglong2*)whh;

    // loader mapping: thread -> (tile row r, kq offset). 16 consecutive
    // threads cover 256B contiguous of one weight row.
    const int r    = tid >> 4;          // 0..31
    const int kqo  = tid & 15;          // 0..15
    const int Rrow = (r >> 3) * 1024 + cta * 8 + (r & 7);
    const unsigned dst0 = (unsigned)__cvta_generic_to_shared(&w_s[(size_t)r * 64 + kqo * 4]);
    const unsigned dst1 = dst0 + 2048 * 4;   // buffer 1 offset (bytes)

    // prefetch stage 0
    {
        int kq = kqo;
        const ulonglong2* src = (kq < RSQ) ? (Wih + (size_t)Rrow * RSQ + kq)
                                           : (Whh + (size_t)Rrow * 256 + (kq - RSQ));
        cp16(dst0, src);
        cp_commit();
    }

    const int g = wi >> 1, ks = wi & 1;
    ull a0 = 0, a1 = 0, a2 = 0, a3 = 0;

    for (int s = 0; s < NST; s++) {
        int buf = s & 1;
        if (s + 1 < NST) {
            int kq = (s + 1) * 16 + kqo;
            const ulonglong2* src = (kq < RSQ) ? (Wih + (size_t)Rrow * RSQ + kq)
                                               : (Whh + (size_t)Rrow * 256 + (kq - RSQ));
            cp16(buf ? dst0 : dst1, src);
            cp_commit();
            cp_wait1();
        } else {
            cp_wait0();
        }
        __syncthreads();

        // x pointer for this stage (stage lies entirely in one segment)
        int kqb = s * 16;
        const ulonglong2* xp;
        if (kqb < LAQ)              xp = (const ulonglong2*)xA    + (size_t)kqb * B;
        else if (kqb < LAQ + 128)   xp = (const ulonglong2*)ctx   + (size_t)(kqb - LAQ) * B;
        else                        xp = (const ulonglong2*)hprev + (size_t)(kqb - LAQ - 128) * B;

        const float* wb = w_s + buf * 2048;
        const ulonglong2* w0 = (const ulonglong2*)(wb + (0 * 8 + g) * 64);
        const ulonglong2* w1 = (const ulonglong2*)(wb + (1 * 8 + g) * 64);
        const ulonglong2* w2 = (const ulonglong2*)(wb + (2 * 8 + g) * 64);
        const ulonglong2* w3 = (const ulonglong2*)(wb + (3 * 8 + g) * 64);

        int q0 = ks * 8;
#pragma unroll
        for (int q = 0; q < 8; q++) {
            int kq = q0 + q;
            ulonglong2 xv = xp[(size_t)kq * B + lane];
            ulonglong2 p0 = w0[kq], p1 = w1[kq], p2 = w2[kq], p3 = w3[kq];
            fma2(a0, p0.x, xv.x); fma2(a0, p0.y, xv.y);
            fma2(a1, p1.x, xv.x); fma2(a1, p1.y, xv.y);
            fma2(a2, p2.x, xv.x); fma2(a2, p2.y, xv.y);
            fma2(a3, p3.x, xv.x); fma2(a3, p3.y, xv.y);
        }
        __syncthreads();                // done with buf before it is refilled
    }

    // cross-warp (half-K) reduction
    int base = ((g * 2 + ks) * 4) * 32 + lane;
    s_red[base]      = hsum(a0);
    s_red[base + 32] = hsum(a1);
    s_red[base + 64] = hsum(a2);
    s_red[base + 96] = hsum(a3);
    __syncthreads();
    if (ks == 0) {
        int u  = cta * 8 + g;
        int b0 = ((g * 2 + 0) * 4) * 32 + lane;
        int b1 = ((g * 2 + 1) * 4) * 32 + lane;
        float gi = s_red[b0]      + s_red[b1]      + bias[u];
        float gf = s_red[b0 + 32] + s_red[b1 + 32] + bias[u + 1024];
        float gg = s_red[b0 + 64] + s_red[b1 + 64] + bias[u + 2048];
        float go = s_red[b0 + 96] + s_red[b1 + 96] + bias[u + 3072];
        float c  = cst[u * 32 + lane];
        float c2 = fsig(gf) * c + fsig(gi) * ftanh(gg);
        float h2 = fsig(go) * ftanh(c2);
        cst[u * 32 + lane] = c2;
        hout[(u >> 2) * 128 + lane * 4 + (u & 3)] = h2;
    }
}

// ---------------------------------------------------------------------------
// the persistent kernel
// ---------------------------------------------------------------------------
__global__ void __launch_bounds__(NTHR, 1) k_main(
    const float* __restrict__ memory, const float* __restrict__ dec_in,
    const int*   __restrict__ memlen,
    const float* __restrict__ prenet_w1, const float* __restrict__ prenet_w2,
    const float* __restrict__ att_wih, const float* __restrict__ att_whh,
    const float* __restrict__ att_b,
    const float* __restrict__ wq, const float* __restrict__ wm,
    const float* __restrict__ v,
    const float* __restrict__ loc_conv, const float* __restrict__ loc_dense,
    const float* __restrict__ dec_wih, const float* __restrict__ dec_whh,
    const float* __restrict__ dec_b,
    const float* __restrict__ proj_w, const float* __restrict__ proj_b,
    const float* __restrict__ gate_w, const float* __restrict__ gate_b,
    float* __restrict__ out) {

    __shared__ float s_u[6144];       // union: lstm weight tiles + reduce | phase scratch
    __shared__ float s_dense[4096];   // loc_dense
    __shared__ float s_lc[1984];      // loc_conv

    const int cta = blockIdx.x;
    const int tid = threadIdx.x;
    const int wi = tid >> 5, lane = tid & 31;
    unsigned gen = 0;

    for (int i = tid; i < 1984; i += NTHR) s_lc[i] = loc_conv[i];
    for (int i = tid; i < 4096; i += NTHR) s_dense[i] = loc_dense[i];

    // ---- zero recurrent state ----
    for (int i = cta * NTHR + tid; i < 1024 * B; i += NBLK * NTHR) {
        g_ac[i] = 0.f; g_dc[i] = 0.f;
        g_ah[0][i] = 0.f; g_ah[1][i] = 0.f;
        g_dh[0][i] = 0.f; g_dh[1][i] = 0.f;
    }
    for (int i = cta * NTHR + tid; i < 512 * B; i += NBLK * NTHR) g_ctx[i] = 0.f;
    for (int i = cta * NTHR + tid; i < B * TIN; i += NBLK * NTHR) { g_aw[i] = 0.f; g_awc[i] = 0.f; }

    // ---- prenet for all 512 steps (64 rounds x 2 groups of 256 threads) ----
    {
        int grp = tid >> 8, sub = tid & 255;
        float* sd = s_u + grp * 512;
        float* sx = sd + 96;
        for (int r = 0; r < 64; r++) {
            int job = r * 256 + cta * 2 + grp;
            int t = job >> 5, b = job & 31;
            __syncthreads();
            if (sub < 80)
                sd[sub] = (t == 0) ? 0.f : dec_in[(size_t)b * NMEL * TOUT + sub * TOUT + (t - 1)];
            __syncthreads();
            float s = 0.f;
            const float* w = prenet_w1 + sub * 80;
#pragma unroll 8
            for (int m = 0; m < 80; m++) s += w[m] * sd[m];
            sx[sub] = fmaxf(s, 0.f);
            __syncthreads();
            s = 0.f;
            const float* w2 = prenet_w2 + sub * 256;
#pragma unroll 8
            for (int m = 0; m < 256; m++) s += w2[m] * sx[m];
            s = fmaxf(s, 0.f);
            g_P[(size_t)t * 8192 + (sub >> 2) * 128 + b * 4 + (sub & 3)] = s;
        }
    }

    // ---- processed_memory + memory transpose (16 rounds x 4 groups of 128) ----
    {
        int grp = tid >> 7, sub = tid & 127;
        float* sm = s_u + grp * 512;
        for (int r = 0; r < 16; r++) {
            int job = r * 512 + cta * 4 + grp;
            int tt = job >> 5, b = job & 31;
            __syncthreads();
            for (int e = sub; e < 512; e += 128) {
                float vv = memory[((size_t)b * TIN + tt) * 512 + e];
                sm[e] = vv;
                g_memT[((size_t)b * 512 + e) * TIN + tt] = vv;
            }
            __syncthreads();
            float s = 0.f;
            const float* w = wm + sub * 512;
#pragma unroll 8
            for (int e = 0; e < 512; e++) s += w[e] * sm[e];
            g_pm[((size_t)b * TIN + tt) * 128 + sub] = s;
        }
    }

    gbar(gen);

    // ======================= main recurrence =======================
    for (int t = 0; t < TOUT; t++) {
        int p = t & 1;

        // ---- P1: attention LSTM ----
        lstm_phase<64>(att_wih, att_whh, att_b,
                       g_P + (size_t)t * 8192, g_ctx, g_ah[p],
                       g_ac, g_ah[p ^ 1], cta, wi, lane, tid, s_u);
        gbar(gen);

        // ---- P2: pq = ah @ wq^T (CTAs 0..15) ----
        __syncthreads();
        {
            int g = wi >> 1, ks = wi & 1;
            if (cta < 16) {
                int a = cta * 8 + g;
                ull acc = 0;
                dot1(acc, (const ulonglong2*)wq + (size_t)a * 256 + ks * 128,
                     (const ulonglong2*)g_ah[p ^ 1] + (size_t)ks * 128 * B, 128, lane);
                s_u[(g * 2 + ks) * 32 + lane] = hsum(acc);
            }
            __syncthreads();
            if (cta < 16 && ks == 0) {
                int a = cta * 8 + g;
                g_pq[lane * 128 + a] = s_u[(g * 2) * 32 + lane] + s_u[(g * 2 + 1) * 32 + lane];
            }
        }
        gbar(gen);

        // ---- P3: energies (2 tiles per CTA, 256 threads each) ----
        {
            int ts = tid >> 8, sub = tid & 255;
            int tile = cta * 2 + ts;            // 0..255 = 8 t-tiles x 32 b
            int b = tile >> 3;
            int t0 = (tile & 7) * 32;
            float* scr  = s_u + ts * 1600;
            float* cat  = scr;                  // [2][64]
            float* co   = scr + 128;            // [32][33]
            float* spq  = scr + 1184;           // [128]
            float* part = scr + 1312;           // [256]
            if (sub < 124) {
                int c = sub / 62, tl = sub % 62;
                int tg = t0 - 15 + tl;
                float vv = 0.f;
                if (tg >= 0 && tg < TIN) vv = (c ? g_awc : g_aw)[b * TIN + tg];
                cat[c * 64 + tl] = vv;
            }
            if (sub < 128) spq[sub] = g_pq[b * 128 + sub];
            __syncthreads();
#pragma unroll
            for (int j = 0; j < 4; j++) {
                int id = sub + j * 256;
                int tl = id >> 5, f = id & 31;
                const float* lc = &s_lc[f * 62];
                float s = 0.f;
#pragma unroll
                for (int k = 0; k < 31; k++) s += lc[k] * cat[tl + k];
#pragma unroll
                for (int k = 0; k < 31; k++) s += lc[31 + k] * cat[64 + tl + k];
                co[tl * 33 + f] = s;
            }
            __syncthreads();
            {
                int tl = sub >> 3, a0i = (sub & 7) * 16;
                const float* pmrow = g_pm + ((size_t)(b * TIN + t0 + tl)) * 128;
                float acc = 0.f;
#pragma unroll 2
                for (int a = a0i; a < a0i + 16; a++) {
                    const float* dw = &s_dense[a * 32];
                    float loc = 0.f;
#pragma unroll
                    for (int f = 0; f < 32; f++) loc += dw[f] * co[tl * 33 + f];
                    acc += ftanh(spq[a] + pmrow[a] + loc) * v[a];
                }
                part[tl * 8 + (sub & 7)] = acc;
            }
            __syncthreads();
            if (sub < 32) {
                float e = 0.f;
#pragma unroll
                for (int j = 0; j < 8; j++) e += part[sub * 8 + j];
                int tg = t0 + sub;
                if (tg >= memlen[b]) e = -1e9f;
                g_e[b * TIN + tg] = e;
            }
        }
        gbar(gen);

        // ---- P4: softmax + context (CTA -> (b, e-quarter)) ----
        {
            int b = cta >> 2, x = cta & 3;
            float* s_w  = s_u;
            float* red  = s_u + 256;
            float* bval = s_u + 266;
            float e = (tid < 256) ? g_e[b * 256 + tid] : -1e30f;
            float m = e;
#pragma unroll
            for (int o = 16; o; o >>= 1) m = fmaxf(m, __shfl_xor_sync(0xffffffffu, m, o));
            if (lane == 0 && tid < 256) red[wi] = m;
            __syncthreads();
            if (tid == 0) {
                float mm = red[0];
#pragma unroll
                for (int i = 1; i < 8; i++) mm = fmaxf(mm, red[i]);
                bval[0] = mm;
            }
            __syncthreads();
            float w0 = (tid < 256) ? __expf(e - bval[0]) : 0.f;
            float ssum = w0;
#pragma unroll
            for (int o = 16; o; o >>= 1) ssum += __shfl_xor_sync(0xffffffffu, ssum, o);
            if (lane == 0 && tid < 256) red[wi] = ssum;
            __syncthreads();
            if (tid == 0) {
                float tt2 = 0.f;
#pragma unroll
                for (int i = 0; i < 8; i++) tt2 += red[i];
                bval[1] = tt2;
            }
            __syncthreads();
            if (tid < 256) {
                float wgt = w0 * __fdividef(1.f, bval[1]);
                s_w[tid] = wgt;
                if (x == 0) {
                    g_aw[b * 256 + tid] = wgt;
                    g_awc[b * 256 + tid] += wgt;
                    out[ALIGN_OFF + (size_t)(b * TOUT + t) * TIN + tid] = wgt;
                }
            }
            __syncthreads();
            if (tid < 256) {
                int ebase = x * 128 + wi * 16;
#pragma unroll 2
                for (int i = 0; i < 16; i++) {
                    int e2 = ebase + i;
                    const float* mrow = g_memT + ((size_t)b * 512 + e2) * TIN;
                    float s = 0.f;
#pragma unroll
                    for (int j = 0; j < 8; j++) {
                        int tt3 = lane + 32 * j;
                        s += mrow[tt3] * s_w[tt3];
                    }
#pragma unroll
                    for (int o = 16; o; o >>= 1) s += __shfl_down_sync(0xffffffffu, s, o);
                    if (lane == 0)
                        g_ctx[(e2 >> 2) * 128 + b * 4 + (e2 & 3)] = s;
                }
            }
        }
        gbar(gen);

        // ---- P5: decoder LSTM ----
        lstm_phase<256>(dec_wih, dec_whh, dec_b,
                        g_ah[p ^ 1], g_ctx, g_dh[p],
                        g_dc, g_dh[p ^ 1], cta, wi, lane, tid, s_u);
        gbar(gen);

        // ---- P6: projection + gate (CTAs 0..10; no trailing barrier) ----
        __syncthreads();
        {
            int g = wi >> 1, ks = wi & 1;
            int o = cta * 8 + g;
            if (cta < 11 && o < 81) {
                const ulonglong2* W = (o < 80) ? ((const ulonglong2*)proj_w + (size_t)o * 384)
                                               : (const ulonglong2*)gate_w;
                const ulonglong2* XD = (const ulonglong2*)g_dh[p ^ 1];
                const ulonglong2* XC = (const ulonglong2*)g_ctx;
                int k0 = ks * 192, k1 = k0 + 192;
                ull acc = 0;
                {
                    int lo = k0, hi = (k1 < 256) ? k1 : 256, n = hi - lo;
                    if (n > 0) dot1(acc, W + lo, XD + (size_t)lo * B, n, lane);
                }
                {
                    int lo = (k0 > 256) ? k0 : 256, hi = k1, n = hi - lo;
                    if (n > 0) dot1(acc, W + lo, XC + (size_t)(lo - 256) * B, n, lane);
                }
                s_u[(g * 2 + ks) * 32 + lane] = hsum(acc);
            }
            __syncthreads();
            if (cta < 11 && o < 81 && ks == 0) {
                float s = s_u[(g * 2) * 32 + lane] + s_u[(g * 2 + 1) * 32 + lane]
                        + ((o < 80) ? proj_b[o] : gate_b[0]);
                if (o < 80)
                    out[(size_t)(lane * NMEL + o) * TOUT + t] = s;
                else
                    out[GATE_OFF + (size_t)lane * TOUT + t] = s;
            }
        }
    }
}

// ---------------------------------------------------------------------------
// launch: 2 graph nodes total
// ---------------------------------------------------------------------------
extern "C" void kernel_launch(void* const* d_in, const int* in_sizes, int n_in,
                              void* d_out, int out_size) {
    const float* memory    = (const float*)d_in[0];
    const float* dec_in    = (const float*)d_in[1];
    const int*   memlen    = (const int*)  d_in[2];
    const float* prenet_w1 = (const float*)d_in[3];
    const float* prenet_w2 = (const float*)d_in[4];
    const float* att_wih   = (const float*)d_in[5];
    const float* att_whh   = (const float*)d_in[6];
    const float* att_b     = (const float*)d_in[7];
    const float* wq        = (const float*)d_in[8];
    const float* wm        = (const float*)d_in[9];
    const float* v         = (const float*)d_in[10];
    const float* loc_conv  = (const float*)d_in[11];
    const float* loc_dense = (const float*)d_in[12];
    const float* dec_wih   = (const float*)d_in[13];
    const float* dec_whh   = (const float*)d_in[14];
    const float* dec_b     = (const float*)d_in[15];
    const float* proj_w    = (const float*)d_in[16];
    const float* proj_b    = (const float*)d_in[17];
    const float* gate_w    = (const float*)d_in[18];
    const float* gate_b    = (const float*)d_in[19];
    float* out = (float*)d_out;

    k_reset<<<1, 32>>>();
    k_main<<<NBLK, NTHR>>>(memory, dec_in, memlen, prenet_w1, prenet_w2,
                           att_wih, att_whh, att_b, wq, wm, v,
                           loc_conv, loc_dense, dec_wih, dec_whh, dec_b,
                           proj_w, proj_b, gate_w, gate_b, out);
}

// round 5
// speedup vs baseline: 1.4080x; 1.2288x over previous
#include <cuda_runtime.h>
#include <math.h>

#define B      32
#define TIN    256
#define TOUT   512
#define NMEL   80
#define NBLK   128
#define NTHR   512

#define GATE_OFF  (B*NMEL*TOUT)
#define ALIGN_OFF (GATE_OFF + B*TOUT)

typedef unsigned long long ull;

// ---------------------------------------------------------------------------
// packed fp32x2 + fast transcendental helpers
// ---------------------------------------------------------------------------
__device__ __forceinline__ void fma2(ull &d, ull a, ull b) {
    asm("fma.rn.f32x2 %0, %1, %2, %3;" : "=l"(d) : "l"(a), "l"(b), "l"(d));
}
__device__ __forceinline__ float hsum(ull v) {
    float a, b;
    asm("mov.b64 {%0,%1}, %2;" : "=f"(a), "=f"(b) : "l"(v));
    return a + b;
}
__device__ __forceinline__ float ftanh(float x) {
    float y;
    asm("tanh.approx.f32 %0, %1;" : "=f"(y) : "f"(x));
    return y;
}
__device__ __forceinline__ float fsig(float x) {
    return fmaf(ftanh(x * 0.5f), 0.5f, 0.5f);
}
__device__ __forceinline__ unsigned smem_u32(const void* p) {
    return (unsigned)__cvta_generic_to_shared(p);
}

// ---------------------------------------------------------------------------
// device-global state. Activation packing: float (k, b) at
// (k>>2)*4*B + b*4 + (k&3); as ulonglong2: index (k>>2)*B + b.
// ---------------------------------------------------------------------------
__device__ __align__(16) float g_P[TOUT * 256 * B];     // prenet out, packed
__device__ __align__(16) float g_pm[B * 128 * TIN];     // processed_memory TRANSPOSED [b][a][t]
__device__ __align__(16) float g_memT[B * 512 * TIN];   // memory transposed [b][e][t]
__device__ __align__(16) float g_ctx[512 * B];          // context, packed
__device__ __align__(16) float g_ah[2][1024 * B];       // att h ping-pong, packed
__device__ __align__(16) float g_ac[1024 * B];
__device__ __align__(16) float g_dh[2][1024 * B];       // dec h ping-pong, packed
__device__ __align__(16) float g_dc[1024 * B];
__device__ float g_aw[B * TIN];
__device__ float g_awc[B * TIN];
__device__ float g_e[B * TIN];
__device__ float g_pq[B * 128];
__device__ volatile unsigned g_gen;
__device__ unsigned g_cnt;

// ---------------------------------------------------------------------------
// grid barrier (all 128 CTAs co-resident, 1/SM)
// ---------------------------------------------------------------------------
__device__ __forceinline__ void gbar(unsigned &gen) {
    gen++;
    __threadfence();
    __syncthreads();
    if (threadIdx.x == 0) {
        if (atomicAdd(&g_cnt, 1u) == NBLK - 1) {
            g_cnt = 0;
            __threadfence();
            g_gen = gen;
        } else {
            while (g_gen < gen) { }
        }
    }
    __syncthreads();
}

__global__ void k_reset() { g_gen = 0; g_cnt = 0; }

// ---------------------------------------------------------------------------
// small dot helper for pq / proj
// ---------------------------------------------------------------------------
__device__ __forceinline__ void dot1(ull &a,
    const ulonglong2* __restrict__ w, const ulonglong2* __restrict__ x,
    int n, int lane) {
#pragma unroll 2
    for (int i = 0; i < n; i++) {
        ulonglong2 xv = x[i * B + lane];
        ulonglong2 wv = w[i];
        fma2(a, wv.x, xv.x); fma2(a, wv.y, xv.y);
    }
}

// ---------------------------------------------------------------------------
// cp.async helpers
// ---------------------------------------------------------------------------
__device__ __forceinline__ void cp16(unsigned dst, const void* src) {
    asm volatile("cp.async.cg.shared.global [%0], [%1], 16;" :: "r"(dst), "l"(src) : "memory");
}
__device__ __forceinline__ void cp_commit() {
    asm volatile("cp.async.commit_group;" ::: "memory");
}
__device__ __forceinline__ void cp_wait1() {
    asm volatile("cp.async.wait_group 1;" ::: "memory");
}
__device__ __forceinline__ void cp_wait0() {
    asm volatile("cp.async.wait_group 0;" ::: "memory");
}

// ---------------------------------------------------------------------------
// LSTM phase: both WEIGHTS and X staged in smem, double-buffered.
// Stage = 16 q-units (16B each). Per stage: w tile 32 rows x 16 kq = 8KB,
// x tile 16 kq x 32 b = 8KB. 512 threads: tid<256 load w (2 cp16),
// tid>=256 load x (2 cp16).
// Warp (up = wi>>2, ks = wi&3): computes 2 u-groups (8 gate rows,
// rows gate*8 + up*2 + j) over kq quarter ks*4..+3 of each stage.
// Cross-warp reduce: shared atomicAdd into bias-initialized s_red[1024].
// ---------------------------------------------------------------------------
template<int LAQ>
__device__ __forceinline__ void lstm_phase(
    const float* __restrict__ wih, const float* __restrict__ whh,
    const float* __restrict__ bias,
    const float* __restrict__ xA, const float* __restrict__ ctx,
    const float* __restrict__ hprev,
    float* __restrict__ cst, float* __restrict__ hout,
    int cta, int tid, float* s_w, float* s_x, float* s_red) {

    const int RSQ = LAQ + 128;          // wih row stride, q-units
    const int KQ  = LAQ + 384;          // total K, q-units
    const int NST = KQ / 16;
    const int wi = tid >> 5, lane = tid & 31;

    __syncthreads();                    // protect smem reuse vs previous phase

    // init reduction buffer with bias (row = gate*8 + uoff)
    for (int i = tid; i < 1024; i += NTHR) {
        int row = i >> 5;
        s_red[i] = bias[(row >> 3) * 1024 + cta * 8 + (row & 7)];
    }

    const ulonglong2* Wih = (const ulonglong2*)wih;
    const ulonglong2* Whh = (const ulonglong2*)whh;

    const bool isW = tid < 256;
    const int unit = (isW ? tid : tid - 256) * 2;   // even; unit+1 same row
    const int wrow = unit >> 4, wkq = unit & 15;
    const long Rbase = (long)((wrow >> 3) * 1024 + cta * 8 + (wrow & 7));
    const unsigned dW = smem_u32(s_w) + unit * 16;
    const unsigned dX = smem_u32(s_x) + unit * 16;

#define LSTM_ISSUE(S, BUF) do {                                             \
        if (isW) {                                                          \
            int kqg = (S) * 16 + wkq;                                       \
            const ulonglong2* src = (kqg < RSQ)                             \
                ? (Wih + Rbase * RSQ + kqg)                                 \
                : (Whh + Rbase * 256 + (kqg - RSQ));                        \
            unsigned d = dW + (BUF) * 8192;                                 \
            cp16(d, src); cp16(d + 16, src + 1);                            \
        } else {                                                            \
            int qu = (S) * 16;                                              \
            const ulonglong2* xb;                                           \
            if (qu < LAQ) xb = (const ulonglong2*)xA + (size_t)qu * B;      \
            else if (qu < LAQ + 128)                                        \
                xb = (const ulonglong2*)ctx + (size_t)(qu - LAQ) * B;       \
            else xb = (const ulonglong2*)hprev + (size_t)(qu - LAQ - 128) * B; \
            unsigned d = dX + (BUF) * 8192;                                 \
            cp16(d, xb + unit); cp16(d + 16, xb + unit + 1);                \
        }                                                                   \
    } while (0)

    LSTM_ISSUE(0, 0);
    cp_commit();

    const int up = wi >> 2, ks = wi & 3;
    ull acc[8];
#pragma unroll
    for (int i = 0; i < 8; i++) acc[i] = 0;

    for (int s = 0; s < NST; s++) {
        int buf = s & 1;
        if (s + 1 < NST) { LSTM_ISSUE(s + 1, buf ^ 1); cp_commit(); cp_wait1(); }
        else             { cp_wait0(); }
        __syncthreads();

        const float* wb = s_w + buf * 2048;
        const ulonglong2* xb = (const ulonglong2*)(s_x + buf * 2048);
#pragma unroll
        for (int q = 0; q < 4; q++) {
            int kq = ks * 4 + q;
            ulonglong2 xv = xb[kq * B + lane];
#pragma unroll
            for (int gate = 0; gate < 4; gate++) {
#pragma unroll
                for (int j = 0; j < 2; j++) {
                    ulonglong2 wv =
                        ((const ulonglong2*)(wb + (gate * 8 + up * 2 + j) * 64))[kq];
                    fma2(acc[gate * 2 + j], wv.x, xv.x);
                    fma2(acc[gate * 2 + j], wv.y, xv.y);
                }
            }
        }
        __syncthreads();
    }
#undef LSTM_ISSUE

#pragma unroll
    for (int gate = 0; gate < 4; gate++)
#pragma unroll
        for (int j = 0; j < 2; j++)
            atomicAdd(&s_red[(gate * 8 + up * 2 + j) * 32 + lane],
                      hsum(acc[gate * 2 + j]));
    __syncthreads();

    if (tid < 256) {
        int uoff = tid >> 5, ln = tid & 31;
        int u = cta * 8 + uoff;
        float gi = s_red[(uoff)      * 32 + ln];
        float gf = s_red[(8  + uoff) * 32 + ln];
        float gg = s_red[(16 + uoff) * 32 + ln];
        float go = s_red[(24 + uoff) * 32 + ln];
        float c  = cst[u * 32 + ln];
        float c2 = fsig(gf) * c + fsig(gi) * ftanh(gg);
        float h2 = fsig(go) * ftanh(c2);
        cst[u * 32 + ln] = c2;
        hout[(u >> 2) * 128 + ln * 4 + (u & 3)] = h2;
    }
}

// ---------------------------------------------------------------------------
// the persistent kernel
// ---------------------------------------------------------------------------
__global__ void __launch_bounds__(NTHR, 1) k_main(
    const float* __restrict__ memory, const float* __restrict__ dec_in,
    const int*   __restrict__ memlen,
    const float* __restrict__ prenet_w1, const float* __restrict__ prenet_w2,
    const float* __restrict__ att_wih, const float* __restrict__ att_whh,
    const float* __restrict__ att_b,
    const float* __restrict__ wq, const float* __restrict__ wm,
    const float* __restrict__ v,
    const float* __restrict__ loc_conv, const float* __restrict__ loc_dense,
    const float* __restrict__ dec_wih, const float* __restrict__ dec_whh,
    const float* __restrict__ dec_b,
    const float* __restrict__ proj_w, const float* __restrict__ proj_b,
    const float* __restrict__ gate_w, const float* __restrict__ gate_b,
    float* __restrict__ out) {

    __shared__ __align__(16) float s_w[4096];    // lstm w tiles (2 bufs) | energy/prenet/prep scratch
    __shared__ __align__(16) float s_x[4096];    // lstm x tiles (2 bufs) | softmax scratch
    __shared__ __align__(16) float s_red[1024];  // lstm reduce | pq/proj scratch
    __shared__ float s_lc[1984];                 // loc_conv (persistent)

    const int cta = blockIdx.x;
    const int tid = threadIdx.x;
    const int wi = tid >> 5, lane = tid & 31;
    unsigned gen = 0;

    for (int i = tid; i < 1984; i += NTHR) s_lc[i] = loc_conv[i];

    // ---- zero recurrent state ----
    for (int i = cta * NTHR + tid; i < 1024 * B; i += NBLK * NTHR) {
        g_ac[i] = 0.f; g_dc[i] = 0.f;
        g_ah[0][i] = 0.f; g_ah[1][i] = 0.f;
        g_dh[0][i] = 0.f; g_dh[1][i] = 0.f;
    }
    for (int i = cta * NTHR + tid; i < 512 * B; i += NBLK * NTHR) g_ctx[i] = 0.f;
    for (int i = cta * NTHR + tid; i < B * TIN; i += NBLK * NTHR) { g_aw[i] = 0.f; g_awc[i] = 0.f; }

    // ---- prenet for all 512 steps ----
    {
        int grp = tid >> 8, sub = tid & 255;
        float* sd = s_w + grp * 512;
        float* sx = sd + 96;
        for (int r = 0; r < 64; r++) {
            int job = r * 256 + cta * 2 + grp;
            int t = job >> 5, b = job & 31;
            __syncthreads();
            if (sub < 80)
                sd[sub] = (t == 0) ? 0.f : dec_in[(size_t)b * NMEL * TOUT + sub * TOUT + (t - 1)];
            __syncthreads();
            float s = 0.f;
            const float* w = prenet_w1 + sub * 80;
#pragma unroll 8
            for (int m = 0; m < 80; m++) s += w[m] * sd[m];
            sx[sub] = fmaxf(s, 0.f);
            __syncthreads();
            s = 0.f;
            const float* w2 = prenet_w2 + sub * 256;
#pragma unroll 8
            for (int m = 0; m < 256; m++) s += w2[m] * sx[m];
            s = fmaxf(s, 0.f);
            g_P[(size_t)t * 8192 + (sub >> 2) * 128 + b * 4 + (sub & 3)] = s;
        }
    }

    // ---- processed_memory (transposed) + memory transpose ----
    {
        int grp = tid >> 7, sub = tid & 127;
        float* sm = s_w + grp * 512;
        for (int r = 0; r < 16; r++) {
            int job = r * 512 + cta * 4 + grp;
            int tt = job >> 5, b = job & 31;
            __syncthreads();
            for (int e = sub; e < 512; e += 128) {
                float vv = memory[((size_t)b * TIN + tt) * 512 + e];
                sm[e] = vv;
                g_memT[((size_t)b * 512 + e) * TIN + tt] = vv;
            }
            __syncthreads();
            float s = 0.f;
            const float* w = wm + sub * 512;
#pragma unroll 8
            for (int e = 0; e < 512; e++) s += w[e] * sm[e];
            g_pm[((size_t)b * 128 + sub) * TIN + tt] = s;   // transposed [b][a][t]
        }
    }

    gbar(gen);

    // ======================= main recurrence =======================
    for (int t = 0; t < TOUT; t++) {
        int p = t & 1;

        // ---- P1: attention LSTM ----
        lstm_phase<64>(att_wih, att_whh, att_b,
                       g_P + (size_t)t * 8192, g_ctx, g_ah[p],
                       g_ac, g_ah[p ^ 1], cta, tid, s_w, s_x, s_red);
        gbar(gen);

        // ---- P2: pq = ah @ wq^T (CTAs 0..15) ----
        __syncthreads();
        {
            int g = wi >> 1, ks = wi & 1;
            if (cta < 16) {
                int a = cta * 8 + g;
                ull acc = 0;
                dot1(acc, (const ulonglong2*)wq + (size_t)a * 256 + ks * 128,
                     (const ulonglong2*)g_ah[p ^ 1] + (size_t)ks * 128 * B, 128, lane);
                s_red[(g * 2 + ks) * 32 + lane] = hsum(acc);
            }
            __syncthreads();
            if (cta < 16 && ks == 0) {
                int a = cta * 8 + g;
                g_pq[lane * 128 + a] = s_red[(g * 2) * 32 + lane] + s_red[(g * 2 + 1) * 32 + lane];
            }
        }
        gbar(gen);

        // ---- P3: energies (2 tiles per CTA, 256 threads each) ----
        {
            int ts = tid >> 8, sub = tid & 255;
            int tile = cta * 2 + ts;            // 0..255 = (b, t-tile)
            int b = tile >> 3;
            int t0 = (tile & 7) * 32;
            float* scr  = s_w + ts * 1600;
            float* cat  = scr;                  // [2][64]
            float* co   = scr + 128;            // [32][33]
            float* spq  = scr + 1184;           // [128]
            float* part = scr + 1312;           // [8][32]
            if (sub < 124) {
                int c = sub / 62, tl = sub % 62;
                int tg = t0 - 15 + tl;
                float vv = 0.f;
                if (tg >= 0 && tg < TIN) vv = (c ? g_awc : g_aw)[b * TIN + tg];
                cat[c * 64 + tl] = vv;
            }
            if (sub < 128) spq[sub] = g_pq[b * 128 + sub];
            __syncthreads();
            // conv: co[tl][f]
#pragma unroll
            for (int j = 0; j < 4; j++) {
                int id = sub + j * 256;
                int tl = id >> 5, f = id & 31;
                const float* lc = &s_lc[f * 62];
                float s = 0.f;
#pragma unroll
                for (int k = 0; k < 31; k++) s += lc[k] * cat[tl + k];
#pragma unroll
                for (int k = 0; k < 31; k++) s += lc[31 + k] * cat[64 + tl + k];
                co[tl * 33 + f] = s;
            }
            __syncthreads();
            // energies: warp wa handles a in [wa*16, wa*16+16), lane = t-local
            {
                int wa = sub >> 5, tl = sub & 31;
                const float* corow = co + tl * 33;
                const float* pmb = g_pm + ((size_t)b * 128) * TIN + t0 + tl;
                float acc = 0.f;
#pragma unroll 2
                for (int a = wa * 16; a < wa * 16 + 16; a++) {
                    const float* dw = loc_dense + a * 32;
                    float loc = 0.f;
#pragma unroll
                    for (int f = 0; f < 32; f++) loc += __ldg(dw + f) * corow[f];
                    float pmv = pmb[(size_t)a * TIN];
                    acc += ftanh(spq[a] + pmv + loc) * __ldg(v + a);
                }
                part[wa * 32 + tl] = acc;
            }
            __syncthreads();
            if (sub < 32) {
                float e = 0.f;
#pragma unroll
                for (int j = 0; j < 8; j++) e += part[j * 32 + sub];
                int tg = t0 + sub;
                if (tg >= memlen[b]) e = -1e9f;
                g_e[b * TIN + tg] = e;
            }
        }
        gbar(gen);

        // ---- P4: softmax + context (CTA -> (b, e-quarter)) ----
        {
            int b = cta >> 2, x = cta & 3;
            float* s_wgt = s_x;
            float* red   = s_x + 256;
            float* bval  = s_x + 266;
            float e = (tid < 256) ? g_e[b * 256 + tid] : -1e30f;
            float m = e;
#pragma unroll
            for (int o = 16; o; o >>= 1) m = fmaxf(m, __shfl_xor_sync(0xffffffffu, m, o));
            if (lane == 0 && tid < 256) red[wi] = m;
            __syncthreads();
            if (tid == 0) {
                float mm = red[0];
#pragma unroll
                for (int i = 1; i < 8; i++) mm = fmaxf(mm, red[i]);
                bval[0] = mm;
            }
            __syncthreads();
            float w0 = (tid < 256) ? __expf(e - bval[0]) : 0.f;
            float ssum = w0;
#pragma unroll
            for (int o = 16; o; o >>= 1) ssum += __shfl_xor_sync(0xffffffffu, ssum, o);
            if (lane == 0 && tid < 256) red[wi] = ssum;
            __syncthreads();
            if (tid == 0) {
                float tt2 = 0.f;
#pragma unroll
                for (int i = 0; i < 8; i++) tt2 += red[i];
                bval[1] = tt2;
            }
            __syncthreads();
            if (tid < 256) {
                float wgt = w0 * __fdividef(1.f, bval[1]);
                s_wgt[tid] = wgt;
                if (x == 0) {
                    g_aw[b * 256 + tid] = wgt;
                    g_awc[b * 256 + tid] += wgt;
                    out[ALIGN_OFF + (size_t)(b * TOUT + t) * TIN + tid] = wgt;
                }
            }
            __syncthreads();
            if (tid < 256) {
                int ebase = x * 128 + wi * 16;
#pragma unroll 2
                for (int i = 0; i < 16; i++) {
                    int e2 = ebase + i;
                    const float* mrow = g_memT + ((size_t)b * 512 + e2) * TIN;
                    float s = 0.f;
#pragma unroll
                    for (int j = 0; j < 8; j++) {
                        int tt3 = lane + 32 * j;
                        s += mrow[tt3] * s_wgt[tt3];
                    }
#pragma unroll
                    for (int o = 16; o; o >>= 1) s += __shfl_down_sync(0xffffffffu, s, o);
                    if (lane == 0)
                        g_ctx[(e2 >> 2) * 128 + b * 4 + (e2 & 3)] = s;
                }
            }
        }
        gbar(gen);

        // ---- P5: decoder LSTM ----
        lstm_phase<256>(dec_wih, dec_whh, dec_b,
                        g_ah[p ^ 1], g_ctx, g_dh[p],
                        g_dc, g_dh[p ^ 1], cta, tid, s_w, s_x, s_red);
        gbar(gen);

        // ---- P6: projection + gate (CTAs 0..10; no trailing barrier) ----
        __syncthreads();
        {
            int g = wi >> 1, ks = wi & 1;
            int o = cta * 8 + g;
            if (cta < 11 && o < 81) {
                const ulonglong2* W = (o < 80) ? ((const ulonglong2*)proj_w + (size_t)o * 384)
                                               : (const ulonglong2*)gate_w;
                const ulonglong2* XD = (const ulonglong2*)g_dh[p ^ 1];
                const ulonglong2* XC = (const ulonglong2*)g_ctx;
                int k0 = ks * 192, k1 = k0 + 192;
                ull acc = 0;
                {
                    int lo = k0, hi = (k1 < 256) ? k1 : 256, n = hi - lo;
                    if (n > 0) dot1(acc, W + lo, XD + (size_t)lo * B, n, lane);
                }
                {
                    int lo = (k0 > 256) ? k0 : 256, hi = k1, n = hi - lo;
                    if (n > 0) dot1(acc, W + lo, XC + (size_t)(lo - 256) * B, n, lane);
                }
                s_red[(g * 2 + ks) * 32 + lane] = hsum(acc);
            }
            __syncthreads();
            if (cta < 11 && o < 81 && ks == 0) {
                float s = s_red[(g * 2) * 32 + lane] + s_red[(g * 2 + 1) * 32 + lane]
                        + ((o < 80) ? proj_b[o] : gate_b[0]);
                if (o < 80)
                    out[(size_t)(lane * NMEL + o) * TOUT + t] = s;
                else
                    out[GATE_OFF + (size_t)lane * TOUT + t] = s;
            }
        }
    }
}

// ---------------------------------------------------------------------------
// launch: 2 graph nodes
// ---------------------------------------------------------------------------
extern "C" void kernel_launch(void* const* d_in, const int* in_sizes, int n_in,
                              void* d_out, int out_size) {
    const float* memory    = (const float*)d_in[0];
    const float* dec_in    = (const float*)d_in[1];
    const int*   memlen    = (const int*)  d_in[2];
    const float* prenet_w1 = (const float*)d_in[3];
    const float* prenet_w2 = (const float*)d_in[4];
    const float* att_wih   = (const float*)d_in[5];
    const float* att_whh   = (const float*)d_in[6];
    const float* att_b     = (const float*)d_in[7];
    const float* wq        = (const float*)d_in[8];
    const float* wm        = (const float*)d_in[9];
    const float* v         = (const float*)d_in[10];
    const float* loc_conv  = (const float*)d_in[11];
    const float* loc_dense = (const float*)d_in[12];
    const float* dec_wih   = (const float*)d_in[13];
    const float* dec_whh   = (const float*)d_in[14];
    const float* dec_b     = (const float*)d_in[15];
    const float* proj_w    = (const float*)d_in[16];
    const float* proj_b    = (const float*)d_in[17];
    const float* gate_w    = (const float*)d_in[18];
    const float* gate_b    = (const float*)d_in[19];
    float* out = (float*)d_out;

    k_reset<<<1, 32>>>();
    k_main<<<NBLK, NTHR>>>(memory, dec_in, memlen, prenet_w1, prenet_w2,
                           att_wih, att_whh, att_b, wq, wm, v,
                           loc_conv, loc_dense, dec_wih, dec_whh, dec_b,
                           proj_w, proj_b, gate_w, gate_b, out);
}

// round 6
// speedup vs baseline: 1.4659x; 1.0411x over previous
#include <cuda_runtime.h>
#include <math.h>

#define B      32
#define TIN    256
#define TOUT   512
#define NMEL   80
#define NBLK   128
#define NTHR   512
#define DSF    24576                 /* dynamic smem floats: 3 bufs x 8192 */
#define DSBYTES (DSF * 4)

#define GATE_OFF  (B*NMEL*TOUT)
#define ALIGN_OFF (GATE_OFF + B*TOUT)

typedef unsigned long long ull;

// ---------------------------------------------------------------------------
// packed fp32x2 + fast transcendental helpers
// ---------------------------------------------------------------------------
__device__ __forceinline__ void fma2(ull &d, ull a, ull b) {
    asm("fma.rn.f32x2 %0, %1, %2, %3;" : "=l"(d) : "l"(a), "l"(b), "l"(d));
}
__device__ __forceinline__ float hsum(ull v) {
    float a, b;
    asm("mov.b64 {%0,%1}, %2;" : "=f"(a), "=f"(b) : "l"(v));
    return a + b;
}
__device__ __forceinline__ float ftanh(float x) {
    float y;
    asm("tanh.approx.f32 %0, %1;" : "=f"(y) : "f"(x));
    return y;
}
__device__ __forceinline__ float fsig(float x) {
    return fmaf(ftanh(x * 0.5f), 0.5f, 0.5f);
}
__device__ __forceinline__ unsigned smem_u32(const void* p) {
    return (unsigned)__cvta_generic_to_shared(p);
}

// ---------------------------------------------------------------------------
// device-global state. Activation packing: float (k, b) at
// (k>>2)*4*B + b*4 + (k&3); as 16B quad: index (k>>2)*B + b.
// ---------------------------------------------------------------------------
__device__ __align__(16) float g_P[TOUT * 256 * B];     // prenet out, packed
__device__ __align__(16) float g_pm[B * 128 * TIN];     // processed_memory [b][a][t]
__device__ __align__(16) float g_memT[B * 512 * TIN];   // memory transposed [b][e][t]
__device__ __align__(16) float g_ctx[512 * B];          // context, packed
__device__ __align__(16) float g_ah[2][1024 * B];       // att h ping-pong, packed
__device__ __align__(16) float g_ac[1024 * B];
__device__ __align__(16) float g_dh[2][1024 * B];       // dec h ping-pong, packed
__device__ __align__(16) float g_dc[1024 * B];
__device__ float g_aw[B * TIN];
__device__ float g_awc[B * TIN];
__device__ float g_e[B * TIN];
__device__ float g_pq[B * 128];
__device__ volatile unsigned g_gen;
__device__ unsigned g_cnt;

// ---------------------------------------------------------------------------
// grid barrier (all 128 CTAs co-resident, 1/SM)
// ---------------------------------------------------------------------------
__device__ __forceinline__ void gbar(unsigned &gen) {
    gen++;
    __threadfence();
    __syncthreads();
    if (threadIdx.x == 0) {
        if (atomicAdd(&g_cnt, 1u) == NBLK - 1) {
            g_cnt = 0;
            __threadfence();
            g_gen = gen;
        } else {
            while (g_gen < gen) { }
        }
    }
    __syncthreads();
}

__global__ void k_reset() { g_gen = 0; g_cnt = 0; }

// ---------------------------------------------------------------------------
// small dot helper for pq / proj
// ---------------------------------------------------------------------------
__device__ __forceinline__ void dot1(ull &a,
    const ulonglong2* __restrict__ w, const ulonglong2* __restrict__ x,
    int n, int lane) {
#pragma unroll 2
    for (int i = 0; i < n; i++) {
        ulonglong2 xv = x[i * B + lane];
        ulonglong2 wv = w[i];
        fma2(a, wv.x, xv.x); fma2(a, wv.y, xv.y);
    }
}

// ---------------------------------------------------------------------------
// cp.async helpers
// ---------------------------------------------------------------------------
__device__ __forceinline__ void cp16(unsigned dst, const void* src) {
    asm volatile("cp.async.cg.shared.global [%0], [%1], 16;" :: "r"(dst), "l"(src) : "memory");
}
__device__ __forceinline__ void cp_commit() {
    asm volatile("cp.async.commit_group;" ::: "memory");
}
__device__ __forceinline__ void cp_wait1() {
    asm volatile("cp.async.wait_group 1;" ::: "memory");
}
__device__ __forceinline__ void cp_wait0() {
    asm volatile("cp.async.wait_group 0;" ::: "memory");
}

// ---------------------------------------------------------------------------
// LSTM phase: weights + x staged in dynamic smem, 3 buffers, prefetch depth 2,
// ONE __syncthreads per stage. Stage = 32 q-units (128 K-floats).
// Buffer layout (floats): buf*8192 : [0..4095] w tile (32 rows x 32 kq quads),
//                                    [4096..8191] x tile (32 kq x 32 b quads).
// Loader: every thread does 2 w-cp16 + 2 x-cp16 per stage.
// Compute: warp (up = wi>>2, ks = wi&3) -> rows {gate*8 + up*2 + j}, kq
// ks*8..ks*8+7. Reduce: K-partials in ds[0..4095], tree sum + bias.
// ---------------------------------------------------------------------------
template<int LAQ>
__device__ __forceinline__ void lstm_phase(
    const float* __restrict__ wih, const float* __restrict__ whh,
    const float* __restrict__ bias,
    const float* __restrict__ xA, const float* __restrict__ ctx,
    const float* __restrict__ hprev,
    float* __restrict__ cst, float* __restrict__ hout,
    int cta, int tid, float* ds, float* s_red) {

    const int RSQ = LAQ + 128;          // wih row stride, q-units
    const int KQ  = LAQ + 384;          // total K, q-units
    const int NST = KQ / 32;
    const int wi = tid >> 5, lane = tid & 31;

    __syncthreads();                    // guard ds reuse vs previous phase

    const int r   = tid >> 4;           // w tile row 0..31
    const int kq0 = (tid & 15) * 2;     // kq pair within stage
    const long Rrow = (long)((r >> 3) * 1024 + cta * 8 + (r & 7));
    const ulonglong2* Wih = (const ulonglong2*)wih;
    const ulonglong2* Whh = (const ulonglong2*)whh;
    const unsigned dW = smem_u32(ds) + (unsigned)((r * 32 + kq0) * 16);
    const unsigned dX = smem_u32(ds) + 4096u * 4 + (unsigned)tid * 32;

#define LSTM_ISSUE(S) do {                                                  \
        int buf_ = (S) % 3;                                                 \
        unsigned boff_ = (unsigned)buf_ * 8192 * 4;                         \
        int kqg_ = (S) * 32 + kq0;                                          \
        const ulonglong2* wsrc_ = (kqg_ < RSQ)                              \
            ? (Wih + Rrow * RSQ + kqg_)                                     \
            : (Whh + Rrow * 256 + (kqg_ - RSQ));                            \
        cp16(dW + boff_, wsrc_);                                            \
        cp16(dW + boff_ + 16, wsrc_ + 1);                                   \
        int sb_ = (S) * 32;                                                 \
        const ulonglong2* xb_;                                              \
        if (sb_ < LAQ) xb_ = (const ulonglong2*)xA + (size_t)sb_ * 32;      \
        else if (sb_ < LAQ + 128)                                           \
            xb_ = (const ulonglong2*)ctx + (size_t)(sb_ - LAQ) * 32;        \
        else xb_ = (const ulonglong2*)hprev + (size_t)(sb_ - LAQ - 128) * 32; \
        cp16(dX + boff_, xb_ + tid * 2);                                    \
        cp16(dX + boff_ + 16, xb_ + tid * 2 + 1);                           \
        cp_commit();                                                        \
    } while (0)

    LSTM_ISSUE(0);
    LSTM_ISSUE(1);

    const int ks = wi & 3, up = wi >> 2;
    ull acc[8];
#pragma unroll
    for (int i = 0; i < 8; i++) acc[i] = 0;

    for (int s = 0; s < NST; s++) {
        if (s + 1 < NST) cp_wait1(); else cp_wait0();
        __syncthreads();                 // data(s) ready AND all done reading buf(s-1)
        if (s + 2 < NST) LSTM_ISSUE(s + 2);   // refills buf (s-1)%3 — safe

        const float* wb = ds + (s % 3) * 8192;
        const ulonglong2* xq = (const ulonglong2*)(wb + 4096);
        const ulonglong2* wq2 = (const ulonglong2*)wb;
#pragma unroll
        for (int q = 0; q < 8; q++) {
            int kq = ks * 8 + q;
            ulonglong2 xv = xq[kq * 32 + lane];
#pragma unroll
            for (int gate = 0; gate < 4; gate++) {
#pragma unroll
                for (int j = 0; j < 2; j++) {
                    ulonglong2 wv = wq2[(gate * 8 + up * 2 + j) * 32 + kq];
                    fma2(acc[gate * 2 + j], wv.x, xv.x);
                    fma2(acc[gate * 2 + j], wv.y, xv.y);
                }
            }
        }
    }
#undef LSTM_ISSUE

    // K-split partials into ds[0..4095], tree-reduce, then gates
    __syncthreads();
#pragma unroll
    for (int gate = 0; gate < 4; gate++)
#pragma unroll
        for (int j = 0; j < 2; j++)
            ds[ks * 1024 + (gate * 8 + up * 2 + j) * 32 + lane] =
                hsum(acc[gate * 2 + j]);
    __syncthreads();
    for (int c = tid; c < 1024; c += NTHR) {
        int row = c >> 5;
        s_red[c] = ds[c] + ds[1024 + c] + ds[2048 + c] + ds[3072 + c]
                 + bias[(row >> 3) * 1024 + cta * 8 + (row & 7)];
    }
    __syncthreads();
    if (tid < 256) {
        int uoff = tid >> 5, ln = tid & 31;
        int u = cta * 8 + uoff;
        float gi = s_red[(uoff)      * 32 + ln];
        float gf = s_red[(8  + uoff) * 32 + ln];
        float gg = s_red[(16 + uoff) * 32 + ln];
        float go = s_red[(24 + uoff) * 32 + ln];
        float c  = cst[u * 32 + ln];
        float c2 = fsig(gf) * c + fsig(gi) * ftanh(gg);
        float h2 = fsig(go) * ftanh(c2);
        cst[u * 32 + ln] = c2;
        hout[(u >> 2) * 128 + ln * 4 + (u & 3)] = h2;
    }
}

// ---------------------------------------------------------------------------
// the persistent kernel
// ---------------------------------------------------------------------------
__global__ void __launch_bounds__(NTHR, 1) k_main(
    const float* __restrict__ memory, const float* __restrict__ dec_in,
    const int*   __restrict__ memlen,
    const float* __restrict__ prenet_w1, const float* __restrict__ prenet_w2,
    const float* __restrict__ att_wih, const float* __restrict__ att_whh,
    const float* __restrict__ att_b,
    const float* __restrict__ wq, const float* __restrict__ wm,
    const float* __restrict__ v,
    const float* __restrict__ loc_conv, const float* __restrict__ loc_dense,
    const float* __restrict__ dec_wih, const float* __restrict__ dec_whh,
    const float* __restrict__ dec_b,
    const float* __restrict__ proj_w, const float* __restrict__ proj_b,
    const float* __restrict__ gate_w, const float* __restrict__ gate_b,
    float* __restrict__ out) {

    extern __shared__ __align__(16) float ds[];   // DSF floats
    __shared__ __align__(16) float s_red[1024];
    __shared__ float s_lc[1984];                  // loc_conv (persistent)

    const int cta = blockIdx.x;
    const int tid = threadIdx.x;
    const int wi = tid >> 5, lane = tid & 31;
    unsigned gen = 0;

    for (int i = tid; i < 1984; i += NTHR) s_lc[i] = loc_conv[i];

    // ---- zero recurrent state ----
    for (int i = cta * NTHR + tid; i < 1024 * B; i += NBLK * NTHR) {
        g_ac[i] = 0.f; g_dc[i] = 0.f;
        g_ah[0][i] = 0.f; g_ah[1][i] = 0.f;
        g_dh[0][i] = 0.f; g_dh[1][i] = 0.f;
    }
    for (int i = cta * NTHR + tid; i < 512 * B; i += NBLK * NTHR) g_ctx[i] = 0.f;
    for (int i = cta * NTHR + tid; i < B * TIN; i += NBLK * NTHR) { g_aw[i] = 0.f; g_awc[i] = 0.f; }

    // ---- prenet for all 512 steps ----
    {
        int grp = tid >> 8, sub = tid & 255;
        float* sd = ds + grp * 512;
        float* sx = sd + 96;
        for (int r = 0; r < 64; r++) {
            int job = r * 256 + cta * 2 + grp;
            int t = job >> 5, b = job & 31;
            __syncthreads();
            if (sub < 80)
                sd[sub] = (t == 0) ? 0.f : dec_in[(size_t)b * NMEL * TOUT + sub * TOUT + (t - 1)];
            __syncthreads();
            float s = 0.f;
            const float* w = prenet_w1 + sub * 80;
#pragma unroll 8
            for (int m = 0; m < 80; m++) s += w[m] * sd[m];
            sx[sub] = fmaxf(s, 0.f);
            __syncthreads();
            s = 0.f;
            const float* w2 = prenet_w2 + sub * 256;
#pragma unroll 8
            for (int m = 0; m < 256; m++) s += w2[m] * sx[m];
            s = fmaxf(s, 0.f);
            g_P[(size_t)t * 8192 + (sub >> 2) * 128 + b * 4 + (sub & 3)] = s;
        }
    }

    // ---- processed_memory (transposed) + memory transpose ----
    {
        int grp = tid >> 7, sub = tid & 127;
        float* sm = ds + grp * 512;
        for (int r = 0; r < 16; r++) {
            int job = r * 512 + cta * 4 + grp;
            int tt = job >> 5, b = job & 31;
            __syncthreads();
            for (int e = sub; e < 512; e += 128) {
                float vv = memory[((size_t)b * TIN + tt) * 512 + e];
                sm[e] = vv;
                g_memT[((size_t)b * 512 + e) * TIN + tt] = vv;
            }
            __syncthreads();
            float s = 0.f;
            const float* w = wm + sub * 512;
#pragma unroll 8
            for (int e = 0; e < 512; e++) s += w[e] * sm[e];
            g_pm[((size_t)b * 128 + sub) * TIN + tt] = s;
        }
    }

    gbar(gen);

    // ======================= main recurrence =======================
    for (int t = 0; t < TOUT; t++) {
        int p = t & 1;

        // ---- P1: attention LSTM ----
        lstm_phase<64>(att_wih, att_whh, att_b,
                       g_P + (size_t)t * 8192, g_ctx, g_ah[p],
                       g_ac, g_ah[p ^ 1], cta, tid, ds, s_red);
        gbar(gen);

        // ---- P2: pq = ah @ wq^T (CTAs 0..15) ----
        __syncthreads();
        {
            int g = wi >> 1, ks = wi & 1;
            if (cta < 16) {
                int a = cta * 8 + g;
                ull acc = 0;
                dot1(acc, (const ulonglong2*)wq + (size_t)a * 256 + ks * 128,
                     (const ulonglong2*)g_ah[p ^ 1] + (size_t)ks * 128 * B, 128, lane);
                s_red[(g * 2 + ks) * 32 + lane] = hsum(acc);
            }
            __syncthreads();
            if (cta < 16 && ks == 0) {
                int a = cta * 8 + g;
                g_pq[lane * 128 + a] = s_red[(g * 2) * 32 + lane] + s_red[(g * 2 + 1) * 32 + lane];
            }
        }
        gbar(gen);

        // ---- P3: energies (2 tiles per CTA, 256 threads each) ----
        {
            int ts = tid >> 8, sub = tid & 255;
            int tile = cta * 2 + ts;            // (b, t-tile)
            int b = tile >> 3;
            int t0 = (tile & 7) * 32;
            float* scr  = ds + ts * 1600;
            float* cat  = scr;                  // [2][64]
            float* co   = scr + 128;            // [32][33]
            float* spq  = scr + 1184;           // [128]
            float* part = scr + 1312;           // [8][32]
            if (sub < 124) {
                int c = sub / 62, tl = sub % 62;
                int tg = t0 - 15 + tl;
                float vv = 0.f;
                if (tg >= 0 && tg < TIN) vv = (c ? g_awc : g_aw)[b * TIN + tg];
                cat[c * 64 + tl] = vv;
            }
            if (sub < 128) spq[sub] = g_pq[b * 128 + sub];
            __syncthreads();
#pragma unroll
            for (int j = 0; j < 4; j++) {
                int id = sub + j * 256;
                int tl = id >> 5, f = id & 31;
                const float* lc = &s_lc[f * 62];
                float s = 0.f;
#pragma unroll
                for (int k = 0; k < 31; k++) s += lc[k] * cat[tl + k];
#pragma unroll
                for (int k = 0; k < 31; k++) s += lc[31 + k] * cat[64 + tl + k];
                co[tl * 33 + f] = s;
            }
            __syncthreads();
            {
                int wa = sub >> 5, tl = sub & 31;
                const float* corow = co + tl * 33;
                const float* pmb = g_pm + ((size_t)b * 128) * TIN + t0 + tl;
                float acc = 0.f;
#pragma unroll 2
                for (int a = wa * 16; a < wa * 16 + 16; a++) {
                    const float* dw = loc_dense + a * 32;
                    float loc = 0.f;
#pragma unroll
                    for (int f = 0; f < 32; f++) loc += __ldg(dw + f) * corow[f];
                    float pmv = pmb[(size_t)a * TIN];
                    acc += ftanh(spq[a] + pmv + loc) * __ldg(v + a);
                }
                part[wa * 32 + tl] = acc;
            }
            __syncthreads();
            if (sub < 32) {
                float e = 0.f;
#pragma unroll
                for (int j = 0; j < 8; j++) e += part[j * 32 + sub];
                int tg = t0 + sub;
                if (tg >= memlen[b]) e = -1e9f;
                g_e[b * TIN + tg] = e;
            }
        }
        gbar(gen);

        // ---- P4: softmax + context (CTA -> (b, e-quarter)) ----
        {
            int b = cta >> 2, x = cta & 3;
            float* s_wgt = ds;
            float* red   = ds + 256;
            float* bval  = ds + 266;
            float e = (tid < 256) ? g_e[b * 256 + tid] : -1e30f;
            float m = e;
#pragma unroll
            for (int o = 16; o; o >>= 1) m = fmaxf(m, __shfl_xor_sync(0xffffffffu, m, o));
            if (lane == 0 && tid < 256) red[wi] = m;
            __syncthreads();
            if (tid == 0) {
                float mm = red[0];
#pragma unroll
                for (int i = 1; i < 8; i++) mm = fmaxf(mm, red[i]);
                bval[0] = mm;
            }
            __syncthreads();
            float w0 = (tid < 256) ? __expf(e - bval[0]) : 0.f;
            float ssum = w0;
#pragma unroll
            for (int o = 16; o; o >>= 1) ssum += __shfl_xor_sync(0xffffffffu, ssum, o);
            if (lane == 0 && tid < 256) red[wi] = ssum;
            __syncthreads();
            if (tid == 0) {
                float tt2 = 0.f;
#pragma unroll
                for (int i = 0; i < 8; i++) tt2 += red[i];
                bval[1] = tt2;
            }
            __syncthreads();
            if (tid < 256) {
                float wgt = w0 * __fdividef(1.f, bval[1]);
                s_wgt[tid] = wgt;
                if (x == 0) {
                    g_aw[b * 256 + tid] = wgt;
                    g_awc[b * 256 + tid] += wgt;
                    out[ALIGN_OFF + (size_t)(b * TOUT + t) * TIN + tid] = wgt;
                }
            }
            __syncthreads();
            if (tid < 256) {
                int ebase = x * 128 + wi * 16;
#pragma unroll 2
                for (int i = 0; i < 16; i++) {
                    int e2 = ebase + i;
                    const float* mrow = g_memT + ((size_t)b * 512 + e2) * TIN;
                    float s = 0.f;
#pragma unroll
                    for (int j = 0; j < 8; j++) {
                        int tt3 = lane + 32 * j;
                        s += mrow[tt3] * s_wgt[tt3];
                    }
#pragma unroll
                    for (int o = 16; o; o >>= 1) s += __shfl_down_sync(0xffffffffu, s, o);
                    if (lane == 0)
                        g_ctx[(e2 >> 2) * 128 + b * 4 + (e2 & 3)] = s;
                }
            }
        }
        gbar(gen);

        // ---- P5: decoder LSTM ----
        lstm_phase<256>(dec_wih, dec_whh, dec_b,
                        g_ah[p ^ 1], g_ctx, g_dh[p],
                        g_dc, g_dh[p ^ 1], cta, tid, ds, s_red);
        gbar(gen);

        // ---- P6: projection + gate (CTAs 0..10; no trailing barrier) ----
        __syncthreads();
        {
            int g = wi >> 1, ks = wi & 1;
            int o = cta * 8 + g;
            if (cta < 11 && o < 81) {
                const ulonglong2* W = (o < 80) ? ((const ulonglong2*)proj_w + (size_t)o * 384)
                                               : (const ulonglong2*)gate_w;
                const ulonglong2* XD = (const ulonglong2*)g_dh[p ^ 1];
                const ulonglong2* XC = (const ulonglong2*)g_ctx;
                int k0 = ks * 192, k1 = k0 + 192;
                ull acc = 0;
                {
                    int lo = k0, hi = (k1 < 256) ? k1 : 256, n = hi - lo;
                    if (n > 0) dot1(acc, W + lo, XD + (size_t)lo * B, n, lane);
                }
                {
                    int lo = (k0 > 256) ? k0 : 256, hi = k1, n = hi - lo;
                    if (n > 0) dot1(acc, W + lo, XC + (size_t)(lo - 256) * B, n, lane);
                }
                s_red[(g * 2 + ks) * 32 + lane] = hsum(acc);
            }
            __syncthreads();
            if (cta < 11 && o < 81 && ks == 0) {
                float s = s_red[(g * 2) * 32 + lane] + s_red[(g * 2 + 1) * 32 + lane]
                        + ((o < 80) ? proj_b[o] : gate_b[0]);
                if (o < 80)
                    out[(size_t)(lane * NMEL + o) * TOUT + t] = s;
                else
                    out[GATE_OFF + (size_t)lane * TOUT + t] = s;
            }
        }
    }
}

// ---------------------------------------------------------------------------
// launch: 2 graph nodes
// ---------------------------------------------------------------------------
extern "C" void kernel_launch(void* const* d_in, const int* in_sizes, int n_in,
                              void* d_out, int out_size) {
    const float* memory    = (const float*)d_in[0];
    const float* dec_in    = (const float*)d_in[1];
    const int*   memlen    = (const int*)  d_in[2];
    const float* prenet_w1 = (const float*)d_in[3];
    const float* prenet_w2 = (const float*)d_in[4];
    const float* att_wih   = (const float*)d_in[5];
    const float* att_whh   = (const float*)d_in[6];
    const float* att_b     = (const float*)d_in[7];
    const float* wq        = (const float*)d_in[8];
    const float* wm        = (const float*)d_in[9];
    const float* v         = (const float*)d_in[10];
    const float* loc_conv  = (const float*)d_in[11];
    const float* loc_dense = (const float*)d_in[12];
    const float* dec_wih   = (const float*)d_in[13];
    const float* dec_whh   = (const float*)d_in[14];
    const float* dec_b     = (const float*)d_in[15];
    const float* proj_w    = (const float*)d_in[16];
    const float* proj_b    = (const float*)d_in[17];
    const float* gate_w    = (const float*)d_in[18];
    const float* gate_b    = (const float*)d_in[19];
    float* out = (float*)d_out;

    cudaFuncSetAttribute(k_main, cudaFuncAttributeMaxDynamicSharedMemorySize, DSBYTES);

    k_reset<<<1, 32>>>();
    k_main<<<NBLK, NTHR, DSBYTES>>>(memory, dec_in, memlen, prenet_w1, prenet_w2,
                                    att_wih, att_whh, att_b, wq, wm, v,
                                    loc_conv, loc_dense, dec_wih, dec_whh, dec_b,
                                    proj_w, proj_b, gate_w, gate_b, out);
}

// round 8
// speedup vs baseline: 1.6392x; 1.1182x over previous
#include <cuda_runtime.h>
#include <math.h>

#define B      32
#define TIN    256
#define TOUT   512
#define NMEL   80
#define NBLK   128
#define NTHR   1024
#define DSF    24576                 /* dynamic smem floats: 3 bufs x 8192 */
#define DSBYTES (DSF * 4)

#define GATE_OFF  (B*NMEL*TOUT)
#define ALIGN_OFF (GATE_OFF + B*TOUT)

typedef unsigned long long ull;

// ---------------------------------------------------------------------------
// packed fp32x2 + fast transcendental helpers
// ---------------------------------------------------------------------------
__device__ __forceinline__ void fma2(ull &d, ull a, ull b) {
    asm("fma.rn.f32x2 %0, %1, %2, %3;" : "=l"(d) : "l"(a), "l"(b), "l"(d));
}
__device__ __forceinline__ float hsum(ull v) {
    float a, b;
    asm("mov.b64 {%0,%1}, %2;" : "=f"(a), "=f"(b) : "l"(v));
    return a + b;
}
__device__ __forceinline__ float ftanh(float x) {
    float y;
    asm("tanh.approx.f32 %0, %1;" : "=f"(y) : "f"(x));
    return y;
}
__device__ __forceinline__ float fsig(float x) {
    return fmaf(ftanh(x * 0.5f), 0.5f, 0.5f);
}
__device__ __forceinline__ unsigned smem_u32(const void* p) {
    return (unsigned)__cvta_generic_to_shared(p);
}

// ---------------------------------------------------------------------------
// device-global state. Activation packing: float (k, b) at
// (k>>2)*4*B + b*4 + (k&3); as 16B quad: index (k>>2)*B + b.
// ---------------------------------------------------------------------------
__device__ __align__(16) float g_P[TOUT * 256 * B];     // prenet out, packed
__device__ __align__(16) float g_pm[B * 128 * TIN];     // processed_memory [b][a][t]
__device__ __align__(16) float g_memT[B * 512 * TIN];   // memory transposed [b][e][t]
__device__ __align__(16) float g_ctx[512 * B];          // context, packed
__device__ __align__(16) float g_ah[2][1024 * B];       // att h ping-pong, packed
__device__ __align__(16) float g_ac[1024 * B];
__device__ __align__(16) float g_dh[2][1024 * B];       // dec h ping-pong, packed
__device__ __align__(16) float g_dc[1024 * B];
__device__ float g_aw[B * TIN];
__device__ float g_awc[B * TIN];
__device__ float g_e[B * TIN];
__device__ float g_pq[B * 128];
__device__ volatile unsigned g_gen;
__device__ unsigned g_cnt;

// ---------------------------------------------------------------------------
// grid barrier (all 128 CTAs co-resident, 1/SM)
// ---------------------------------------------------------------------------
__device__ __forceinline__ void gbar(unsigned &gen) {
    gen++;
    __threadfence();
    __syncthreads();
    if (threadIdx.x == 0) {
        if (atomicAdd(&g_cnt, 1u) == NBLK - 1) {
            g_cnt = 0;
            __threadfence();
            g_gen = gen;
        } else {
            while (g_gen < gen) { }
        }
    }
    __syncthreads();
}

__global__ void k_reset() { g_gen = 0; g_cnt = 0; }

// ---------------------------------------------------------------------------
// small dot helper for pq / proj
// ---------------------------------------------------------------------------
__device__ __forceinline__ void dot1(ull &a,
    const ulonglong2* __restrict__ w, const ulonglong2* __restrict__ x,
    int n, int lane) {
#pragma unroll 2
    for (int i = 0; i < n; i++) {
        ulonglong2 xv = x[i * B + lane];
        ulonglong2 wv = w[i];
        fma2(a, wv.x, xv.x); fma2(a, wv.y, xv.y);
    }
}

// ---------------------------------------------------------------------------
// cp.async helpers
// ---------------------------------------------------------------------------
__device__ __forceinline__ void cp16(unsigned dst, const void* src) {
    asm volatile("cp.async.cg.shared.global [%0], [%1], 16;" :: "r"(dst), "l"(src) : "memory");
}
__device__ __forceinline__ void cp_commit() {
    asm volatile("cp.async.commit_group;" ::: "memory");
}
__device__ __forceinline__ void cp_wait1() {
    asm volatile("cp.async.wait_group 1;" ::: "memory");
}
__device__ __forceinline__ void cp_wait0() {
    asm volatile("cp.async.wait_group 0;" ::: "memory");
}

// ---------------------------------------------------------------------------
// LSTM phase: weights + x in dynamic smem, 3 buffers, prefetch depth 2,
// one __syncthreads per stage. Stage = 32 q-units (128 K-floats).
// Buffer (floats): buf*8192: [0..4095] w (32 rows x 32 kq quads),
//                            [4096..8191] x (32 kq x 32 b quads).
// Loader: thread tid loads w quad tid (row tid>>5, kq tid&31) and x quad tid.
// Compute: warp wi -> rows rg*4..rg*4+3 (rg=wi>>2), kq ks*8..ks*8+7 (ks=wi&3).
// Reduce: 4 K-partials per row in ds[0..4095], tree sum + bias.
// ---------------------------------------------------------------------------
template<int LAQ>
__device__ __forceinline__ void lstm_phase(
    const float* __restrict__ wih, const float* __restrict__ whh,
    const float* __restrict__ bias,
    const float* __restrict__ xA, const float* __restrict__ ctx,
    const float* __restrict__ hprev,
    float* __restrict__ cst, float* __restrict__ hout,
    int cta, int tid, float* ds, float* s_red) {

    const int RSQ = LAQ + 128;          // wih row stride, q-units
    const int KQ  = LAQ + 384;          // total K, q-units
    const int NST = KQ / 32;
    const int wi = tid >> 5, lane = tid & 31;

    __syncthreads();                    // guard ds reuse vs previous phase

    const int kq0 = tid & 31;
    const int r   = tid >> 5;
    const long Rrow = (long)((r >> 3) * 1024 + cta * 8 + (r & 7));
    const ulonglong2* Wih = (const ulonglong2*)wih;
    const ulonglong2* Whh = (const ulonglong2*)whh;
    const unsigned dW = smem_u32(ds) + (unsigned)tid * 16;
    const unsigned dX = smem_u32(ds) + 4096u * 4 + (unsigned)tid * 16;

#define LSTM_ISSUE(S) do {                                                  \
        unsigned boff_ = (unsigned)((S) % 3) * 32768u;                      \
        int kqg_ = (S) * 32 + kq0;                                          \
        const ulonglong2* wsrc_ = (kqg_ < RSQ)                              \
            ? (Wih + Rrow * RSQ + kqg_)                                     \
            : (Whh + Rrow * 256 + (kqg_ - RSQ));                            \
        cp16(dW + boff_, wsrc_);                                            \
        int sb_ = (S) * 32;                                                 \
        const ulonglong2* xb_;                                              \
        if (sb_ < LAQ) xb_ = (const ulonglong2*)xA + (size_t)sb_ * 32;      \
        else if (sb_ < LAQ + 128)                                           \
            xb_ = (const ulonglong2*)ctx + (size_t)(sb_ - LAQ) * 32;        \
        else xb_ = (const ulonglong2*)hprev + (size_t)(sb_ - LAQ - 128) * 32; \
        cp16(dX + boff_, xb_ + tid);                                        \
        cp_commit();                                                        \
    } while (0)

    LSTM_ISSUE(0);
    LSTM_ISSUE(1);

    const int ks = wi & 3, rg = wi >> 2;
    ull acc[4];
#pragma unroll
    for (int i = 0; i < 4; i++) acc[i] = 0;

    for (int s = 0; s < NST; s++) {
        if (s + 1 < NST) cp_wait1(); else cp_wait0();
        __syncthreads();                 // data(s) ready; buf(s-1) fully read
        if (s + 2 < NST) LSTM_ISSUE(s + 2);

        const float* wb = ds + (s % 3) * 8192;
        const ulonglong2* xq  = (const ulonglong2*)(wb + 4096);
        const ulonglong2* wq2 = (const ulonglong2*)wb;
#pragma unroll
        for (int q = 0; q < 8; q++) {
            int kq = ks * 8 + q;
            ulonglong2 xv = xq[kq * 32 + lane];
#pragma unroll
            for (int j = 0; j < 4; j++) {
                ulonglong2 wv = wq2[(rg * 4 + j) * 32 + kq];
                fma2(acc[j], wv.x, xv.x);
                fma2(acc[j], wv.y, xv.y);
            }
        }
    }
#undef LSTM_ISSUE

    // K-split partials into ds[0..4095], tree-reduce, then gates
    __syncthreads();
#pragma unroll
    for (int j = 0; j < 4; j++)
        ds[ks * 1024 + (rg * 4 + j) * 32 + lane] = hsum(acc[j]);
    __syncthreads();
    if (tid < 1024) {
        int c = tid;
        int row = c >> 5;
        s_red[c] = ds[c] + ds[1024 + c] + ds[2048 + c] + ds[3072 + c]
                 + bias[(row >> 3) * 1024 + cta * 8 + (row & 7)];
    }
    __syncthreads();
    if (tid < 256) {
        int uoff = tid >> 5, ln = tid & 31;
        int u = cta * 8 + uoff;
        float gi = s_red[(uoff)      * 32 + ln];
        float gf = s_red[(8  + uoff) * 32 + ln];
        float gg = s_red[(16 + uoff) * 32 + ln];
        float go = s_red[(24 + uoff) * 32 + ln];
        float c  = cst[u * 32 + ln];
        float c2 = fsig(gf) * c + fsig(gi) * ftanh(gg);
        float h2 = fsig(go) * ftanh(c2);
        cst[u * 32 + ln] = c2;
        hout[(u >> 2) * 128 + ln * 4 + (u & 3)] = h2;
    }
}

// ---------------------------------------------------------------------------
// the persistent kernel
// ---------------------------------------------------------------------------
__global__ void __launch_bounds__(NTHR, 1) k_main(
    const float* __restrict__ memory, const float* __restrict__ dec_in,
    const int*   __restrict__ memlen,
    const float* __restrict__ prenet_w1, const float* __restrict__ prenet_w2,
    const float* __restrict__ att_wih, const float* __restrict__ att_whh,
    const float* __restrict__ att_b,
    const float* __restrict__ wq, const float* __restrict__ wm,
    const float* __restrict__ v,
    const float* __restrict__ loc_conv, const float* __restrict__ loc_dense,
    const float* __restrict__ dec_wih, const float* __restrict__ dec_whh,
    const float* __restrict__ dec_b,
    const float* __restrict__ proj_w, const float* __restrict__ proj_b,
    const float* __restrict__ gate_w, const float* __restrict__ gate_b,
    float* __restrict__ out) {

    extern __shared__ __align__(16) float ds[];   // DSF floats
    __shared__ __align__(16) float s_red[1024];
    __shared__ float s_lc[1984];                  // loc_conv (persistent)

    const int cta = blockIdx.x;
    const int tid = threadIdx.x;
    const int wi = tid >> 5, lane = tid & 31;
    unsigned gen = 0;

    for (int i = tid; i < 1984; i += NTHR) s_lc[i] = loc_conv[i];

    // ---- zero recurrent state ----
    for (int i = cta * NTHR + tid; i < 1024 * B; i += NBLK * NTHR) {
        g_ac[i] = 0.f; g_dc[i] = 0.f;
        g_ah[0][i] = 0.f; g_ah[1][i] = 0.f;
        g_dh[0][i] = 0.f; g_dh[1][i] = 0.f;
    }
    for (int i = cta * NTHR + tid; i < 512 * B; i += NBLK * NTHR) g_ctx[i] = 0.f;
    for (int i = cta * NTHR + tid; i < B * TIN; i += NBLK * NTHR) { g_aw[i] = 0.f; g_awc[i] = 0.f; }

    // ---- prenet for all 512 steps (32 rounds x 4 groups of 256 threads) ----
    {
        int grp = tid >> 8, sub = tid & 255;
        float* sd = ds + grp * 512;
        float* sx = sd + 96;
        for (int r = 0; r < 32; r++) {
            int job = r * 512 + cta * 4 + grp;
            int t = job >> 5, b = job & 31;
            __syncthreads();
            if (sub < 80)
                sd[sub] = (t == 0) ? 0.f : dec_in[(size_t)b * NMEL * TOUT + sub * TOUT + (t - 1)];
            __syncthreads();
            float s = 0.f;
            const float* w = prenet_w1 + sub * 80;
#pragma unroll 8
            for (int m = 0; m < 80; m++) s += w[m] * sd[m];
            sx[sub] = fmaxf(s, 0.f);
            __syncthreads();
            s = 0.f;
            const float* w2 = prenet_w2 + sub * 256;
#pragma unroll 8
            for (int m = 0; m < 256; m++) s += w2[m] * sx[m];
            s = fmaxf(s, 0.f);
            g_P[(size_t)t * 8192 + (sub >> 2) * 128 + b * 4 + (sub & 3)] = s;
        }
    }

    // ---- processed_memory (transposed) + memory transpose (8 rounds x 8 grp) ----
    {
        int grp = tid >> 7, sub = tid & 127;
        float* sm = ds + grp * 512;
        for (int r = 0; r < 8; r++) {
            int job = r * 1024 + cta * 8 + grp;
            int tt = job >> 5, b = job & 31;
            __syncthreads();
            for (int e = sub; e < 512; e += 128) {
                float vv = memory[((size_t)b * TIN + tt) * 512 + e];
                sm[e] = vv;
                g_memT[((size_t)b * 512 + e) * TIN + tt] = vv;
            }
            __syncthreads();
            float s = 0.f;
            const float* w = wm + sub * 512;
#pragma unroll 8
            for (int e = 0; e < 512; e++) s += w[e] * sm[e];
            g_pm[((size_t)b * 128 + sub) * TIN + tt] = s;
        }
    }

    gbar(gen);

    // ======================= main recurrence =======================
    for (int t = 0; t < TOUT; t++) {
        int p = t & 1;

        // ---- P1: attention LSTM ----
        lstm_phase<64>(att_wih, att_whh, att_b,
                       g_P + (size_t)t * 8192, g_ctx, g_ah[p],
                       g_ac, g_ah[p ^ 1], cta, tid, ds, s_red);
        gbar(gen);

        // ---- P2: pq = ah @ wq^T (CTAs 0..15, 4-way K-split) ----
        __syncthreads();
        {
            int g = wi >> 2, ks = wi & 3;
            if (cta < 16) {
                int a = cta * 8 + g;
                ull acc = 0;
                dot1(acc, (const ulonglong2*)wq + (size_t)a * 256 + ks * 64,
                     (const ulonglong2*)g_ah[p ^ 1] + (size_t)ks * 64 * B, 64, lane);
                s_red[(g * 4 + ks) * 32 + lane] = hsum(acc);
            }
            __syncthreads();
            if (cta < 16 && ks == 0) {
                int a = cta * 8 + g;
                g_pq[lane * 128 + a] = s_red[(g * 4) * 32 + lane] + s_red[(g * 4 + 1) * 32 + lane]
                                     + s_red[(g * 4 + 2) * 32 + lane] + s_red[(g * 4 + 3) * 32 + lane];
            }
        }
        gbar(gen);

        // ---- P3: energies (2 tiles per CTA, 512 threads each) ----
        {
            int ts = tid >> 9, sub = tid & 511;
            int tile = cta * 2 + ts;            // (b, t-tile)
            int b = tile >> 3;
            int t0 = (tile & 7) * 32;
            float* scr  = ds + ts * 2048;
            float* cat  = scr;                  // [2][64]
            float* co   = scr + 128;            // [32][33]
            float* spq  = scr + 1184;           // [128]
            float* part = scr + 1312;           // [16][32]
            if (sub < 124) {
                int c = sub / 62, tl = sub % 62;
                int tg = t0 - 15 + tl;
                float vv = 0.f;
                if (tg >= 0 && tg < TIN) vv = (c ? g_awc : g_aw)[b * TIN + tg];
                cat[c * 64 + tl] = vv;
            }
            if (sub < 128) spq[sub] = g_pq[b * 128 + sub];
            __syncthreads();
#pragma unroll
            for (int j = 0; j < 2; j++) {
                int id = sub + j * 512;
                int tl = id >> 5, f = id & 31;
                const float* lc = &s_lc[f * 62];
                float s = 0.f;
#pragma unroll
                for (int k = 0; k < 31; k++) s += lc[k] * cat[tl + k];
#pragma unroll
                for (int k = 0; k < 31; k++) s += lc[31 + k] * cat[64 + tl + k];
                co[tl * 33 + f] = s;
            }
            __syncthreads();
            {
                int wa = sub >> 5, tl = sub & 31;
                const float* corow = co + tl * 33;
                const float* pmb = g_pm + ((size_t)b * 128) * TIN + t0 + tl;
                float acc = 0.f;
#pragma unroll 2
                for (int a = wa * 8; a < wa * 8 + 8; a++) {
                    const float* dw = loc_dense + a * 32;
                    float loc = 0.f;
#pragma unroll
                    for (int f = 0; f < 32; f++) loc += __ldg(dw + f) * corow[f];
                    float pmv = pmb[(size_t)a * TIN];
                    acc += ftanh(spq[a] + pmv + loc) * __ldg(v + a);
                }
                part[wa * 32 + tl] = acc;
            }
            __syncthreads();
            if (sub < 32) {
                float e = 0.f;
#pragma unroll
                for (int j = 0; j < 16; j++) e += part[j * 32 + sub];
                int tg = t0 + sub;
                if (tg >= memlen[b]) e = -1e9f;
                g_e[b * TIN + tg] = e;
            }
        }
        gbar(gen);

        // ---- P4: softmax + context (CTA -> (b, e-quarter)) ----
        {
            int b = cta >> 2, x = cta & 3;
            float* s_wgt = ds;
            float* red   = ds + 256;
            float* bval  = ds + 266;
            float e = (tid < 256) ? g_e[b * 256 + tid] : -1e30f;
            float m = e;
#pragma unroll
            for (int o = 16; o; o >>= 1) m = fmaxf(m, __shfl_xor_sync(0xffffffffu, m, o));
            if (lane == 0 && tid < 256) red[wi] = m;
            __syncthreads();
            if (tid == 0) {
                float mm = red[0];
#pragma unroll
                for (int i = 1; i < 8; i++) mm = fmaxf(mm, red[i]);
                bval[0] = mm;
            }
            __syncthreads();
            float w0 = (tid < 256) ? __expf(e - bval[0]) : 0.f;
            float ssum = w0;
#pragma unroll
            for (int o = 16; o; o >>= 1) ssum += __shfl_xor_sync(0xffffffffu, ssum, o);
            if (lane == 0 && tid < 256) red[wi] = ssum;
            __syncthreads();
            if (tid == 0) {
                float tt2 = 0.f;
#pragma unroll
                for (int i = 0; i < 8; i++) tt2 += red[i];
                bval[1] = tt2;
            }
            __syncthreads();
            if (tid < 256) {
                float wgt = w0 * __fdividef(1.f, bval[1]);
                s_wgt[tid] = wgt;
                if (x == 0) {
                    g_aw[b * 256 + tid] = wgt;
                    g_awc[b * 256 + tid] += wgt;
                    out[ALIGN_OFF + (size_t)(b * TOUT + t) * TIN + tid] = wgt;
                }
            }
            __syncthreads();
            {
                int ebase = x * 128 + wi * 4;
#pragma unroll
                for (int i = 0; i < 4; i++) {
                    int e2 = ebase + i;
                    const float* mrow = g_memT + ((size_t)b * 512 + e2) * TIN;
                    float s = 0.f;
#pragma unroll
                    for (int j = 0; j < 8; j++) {
                        int tt3 = lane + 32 * j;
                        s += mrow[tt3] * s_wgt[tt3];
                    }
#pragma unroll
                    for (int o = 16; o; o >>= 1) s += __shfl_down_sync(0xffffffffu, s, o);
                    if (lane == 0)
                        g_ctx[(e2 >> 2) * 128 + b * 4 + (e2 & 3)] = s;
                }
            }
        }
        gbar(gen);

        // ---- P5: decoder LSTM ----
        lstm_phase<256>(dec_wih, dec_whh, dec_b,
                        g_ah[p ^ 1], g_ctx, g_dh[p],
                        g_dc, g_dh[p ^ 1], cta, tid, ds, s_red);
        gbar(gen);

        // ---- P6: projection + gate (CTAs 0..10; no trailing barrier) ----
        __syncthreads();
        {
            int g = wi >> 2, ks = wi & 3;
            int o = cta * 8 + g;
            if (cta < 11 && o < 81) {
                const ulonglong2* W = (o < 80) ? ((const ulonglong2*)proj_w + (size_t)o * 384)
                                               : (const ulonglong2*)gate_w;
                const ulonglong2* XD = (const ulonglong2*)g_dh[p ^ 1];
                const ulonglong2* XC = (const ulonglong2*)g_ctx;
                int k0 = ks * 96, k1 = k0 + 96;
                ull acc = 0;
                {
                    int lo = k0, hi = (k1 < 256) ? k1 : 256, n = hi - lo;
                    if (n > 0) dot1(acc, W + lo, XD + (size_t)lo * B, n, lane);
                }
                {
                    int lo = (k0 > 256) ? k0 : 256, hi = k1, n = hi - lo;
                    if (n > 0) dot1(acc, W + lo, XC + (size_t)(lo - 256) * B, n, lane);
                }
                s_red[(g * 4 + ks) * 32 + lane] = hsum(acc);
            }
            __syncthreads();
            if (cta < 11 && o < 81 && ks == 0) {
                float s = s_red[(g * 4) * 32 + lane] + s_red[(g * 4 + 1) * 32 + lane]
                        + s_red[(g * 4 + 2) * 32 + lane] + s_red[(g * 4 + 3) * 32 + lane]
                        + ((o < 80) ? proj_b[o] : gate_b[0]);
                if (o < 80)
                    out[(size_t)(lane * NMEL + o) * TOUT + t] = s;
                else
                    out[GATE_OFF + (size_t)lane * TOUT + t] = s;
            }
        }
    }
}

// ---------------------------------------------------------------------------
// launch: 2 graph nodes
// ---------------------------------------------------------------------------
extern "C" void kernel_launch(void* const* d_in, const int* in_sizes, int n_in,
                              void* d_out, int out_size) {
    const float* memory    = (const float*)d_in[0];
    const float* dec_in    = (const float*)d_in[1];
    const int*   memlen    = (const int*)  d_in[2];
    const float* prenet_w1 = (const float*)d_in[3];
    const float* prenet_w2 = (const float*)d_in[4];
    const float* att_wih   = (const float*)d_in[5];
    const float* att_whh   = (const float*)d_in[6];
    const float* att_b     = (const float*)d_in[7];
    const float* wq        = (const float*)d_in[8];
    const float* wm        = (const float*)d_in[9];
    const float* v         = (const float*)d_in[10];
    const float* loc_conv  = (const float*)d_in[11];
    const float* loc_dense = (const float*)d_in[12];
    const float* dec_wih   = (const float*)d_in[13];
    const float* dec_whh   = (const float*)d_in[14];
    const float* dec_b     = (const float*)d_in[15];
    const float* proj_w    = (const float*)d_in[16];
    const float* proj_b    = (const float*)d_in[17];
    const float* gate_w    = (const float*)d_in[18];
    const float* gate_b    = (const float*)d_in[19];
    float* out = (float*)d_out;

    cudaFuncSetAttribute(k_main, cudaFuncAttributeMaxDynamicSharedMemorySize, DSBYTES);

    k_reset<<<1, 32>>>();
    k_main<<<NBLK, NTHR, DSBYTES>>>(memory, dec_in, memlen, prenet_w1, prenet_w2,
                                    att_wih, att_whh, att_b, wq, wm, v,
                                    loc_conv, loc_dense, dec_wih, dec_whh, dec_b,
                                    proj_w, proj_b, gate_w, gate_b, out);
}

// round 9
// speedup vs baseline: 3.1068x; 1.8953x over previous
#include <cuda_runtime.h>
#include <cuda_bf16.h>
#include <math.h>

#define B      32
#define TIN    256
#define TOUT   512
#define NMEL   80
#define NBLK   128
#define NTHR   1024
#define DSBYTES 65536

#define GATE_OFF  (B*NMEL*TOUT)
#define ALIGN_OFF (GATE_OFF + B*TOUT)

#define NKT_ATT 112      /* 1792 / 16 */
#define NKT_DEC 160      /* 2560 / 16 */

typedef unsigned long long ull;

// ---------------------------------------------------------------------------
// helpers
// ---------------------------------------------------------------------------
__device__ __forceinline__ float ftanh(float x) {
    float y;
    asm("tanh.approx.f32 %0, %1;" : "=f"(y) : "f"(x));
    return y;
}
__device__ __forceinline__ float fsig(float x) {
    return fmaf(ftanh(x * 0.5f), 0.5f, 0.5f);
}

__device__ __forceinline__ void mma_bf(float* d, unsigned a0, unsigned a1,
                                       unsigned a2, unsigned a3,
                                       unsigned b0, unsigned b1) {
    asm volatile(
        "mma.sync.aligned.m16n8k16.row.col.f32.bf16.bf16.f32 "
        "{%0,%1,%2,%3},{%4,%5,%6,%7},{%8,%9},{%0,%1,%2,%3};"
        : "+f"(d[0]), "+f"(d[1]), "+f"(d[2]), "+f"(d[3])
        : "r"(a0), "r"(a1), "r"(a2), "r"(a3), "r"(b0), "r"(b1));
}

// ---------------------------------------------------------------------------
// device-global state
// ---------------------------------------------------------------------------
// fragment-packed weights: [cta][mt][kt][lane][8 words: hi0..3, lo0..3]
__device__ __align__(16) unsigned g_attW[128 * 2 * NKT_ATT * 256];
__device__ __align__(16) unsigned g_decW[128 * 2 * NKT_DEC * 256];
// fragment-packed x buffers: per ktile: [4 nt][32 lane][4 words: bhi0,bhi1,blo0,blo1]
__device__ __align__(16) unsigned g_attP[TOUT * 16 * 512];     // prenet, per t
__device__ __align__(16) unsigned g_attCtx[32 * 512];
__device__ __align__(16) unsigned g_attAh[2][64 * 512];
__device__ __align__(16) unsigned g_decAh[64 * 512];
__device__ __align__(16) unsigned g_decCtx[32 * 512];
__device__ __align__(16) unsigned g_decDh[2][64 * 512];
// fp32 activations for scalar consumers [b][feature]
__device__ __align__(16) float g_ahF[B * 1024];
__device__ __align__(16) float g_dhF[B * 1024];
__device__ __align__(16) float g_ctxF[B * 512];
// cell states [u][b]
__device__ __align__(16) float g_ac[1024 * B];
__device__ __align__(16) float g_dc[1024 * B];
// attention
__device__ __align__(16) float g_pm[B * 128 * TIN];     // processed_memory [b][a][t]
__device__ __align__(16) float g_memT[B * 512 * TIN];   // memory [b][e][t]
__device__ float g_aw[B * TIN];
__device__ float g_awc[B * TIN];
__device__ float g_e[B * TIN];
__device__ float g_pq[B * 128];
__device__ volatile unsigned g_gen;
__device__ unsigned g_cnt;

// ---------------------------------------------------------------------------
// grid barrier (all 128 CTAs co-resident, 1/SM)
// ---------------------------------------------------------------------------
__device__ __forceinline__ void gbar(unsigned &gen) {
    gen++;
    __threadfence();
    __syncthreads();
    if (threadIdx.x == 0) {
        if (atomicAdd(&g_cnt, 1u) == NBLK - 1) {
            g_cnt = 0;
            __threadfence();
            g_gen = gen;
        } else {
            while (g_gen < gen) { }
        }
    }
    __syncthreads();
}

__global__ void k_reset() { g_gen = 0; g_cnt = 0; }

// ---------------------------------------------------------------------------
// x packer: writes bf16 hi+lo of value v at (ktile, kk within tile, batch n)
// fragment layout per ktile: [nt][lane][word: bhi0,bhi1,blo0,blo1]
//   b0 = {B[2t4][g], B[2t4+1][g]}, b1 = {B[2t4+8][g], B[2t4+9][g]}
// ---------------------------------------------------------------------------
__device__ __forceinline__ void pack_x(unsigned* base, int ktile, int kk, int n, float v) {
    int reg = (kk >> 3) & 1;
    int t4  = (kk & 7) >> 1;
    int hl  = kk & 1;
    int lane = (n & 7) * 4 + t4;
    int nt = n >> 3;
    unsigned short* p = (unsigned short*)(base + ((size_t)(ktile * 4 + nt) * 32 + lane) * 4 + reg) + hl;
    __nv_bfloat16 h = __float2bfloat16_rn(v);
    *p = __bfloat16_as_ushort(h);
    float lo = v - __bfloat162float(h);
    *(p + 4) = __bfloat16_as_ushort(__float2bfloat16_rn(lo));   // +2 words
}

// ---------------------------------------------------------------------------
// weight preprocessor: pack into fragment order (CTA packs its own slice)
// A frag (m16k16 row-major): a0=A[g][2t4..+1], a1=A[g+8][..], a2=A[g][2t4+8..],
// a3=A[g+8][2t4+8..]
// ---------------------------------------------------------------------------
__device__ void prep_W(unsigned* dst, const float* wih, const float* whh,
                       int NKT, int LIH, int cta, int tid) {
    int total = 2 * NKT * 32 * 4;
    for (int i = tid; i < total; i += NTHR) {
        int r = i & 3;
        int lane = (i >> 2) & 31;
        int ktm = i >> 7;               // mt*NKT + kt
        int kt = ktm % NKT, mt = ktm / NKT;
        int g = lane >> 2, t4 = lane & 3;
        int rl = mt * 16 + g + (r & 1) * 8;
        int rg = (rl >> 3) * 1024 + cta * 8 + (rl & 7);
        int k = kt * 16 + (r & 2) * 4 + 2 * t4;
        const float* src = (k < LIH) ? (wih + (size_t)rg * LIH + k)
                                     : (whh + (size_t)rg * 1024 + (k - LIH));
        float w0 = src[0], w1 = src[1];
        __nv_bfloat16 h0 = __float2bfloat16_rn(w0), h1 = __float2bfloat16_rn(w1);
        float l0 = w0 - __bfloat162float(h0);
        float l1 = w1 - __bfloat162float(h1);
        unsigned hw = ((unsigned)__bfloat16_as_ushort(h1) << 16) | __bfloat16_as_ushort(h0);
        unsigned lw = ((unsigned)__bfloat16_as_ushort(__float2bfloat16_rn(l1)) << 16)
                    | __bfloat16_as_ushort(__float2bfloat16_rn(l0));
        size_t base = (((size_t)(cta * 2 + mt) * NKT + kt) * 32 + lane) * 8;
        dst[base + r] = hw;
        dst[base + 4 + r] = lw;
    }
}

// ---------------------------------------------------------------------------
// LSTM via MMA. warp = (mt = wi>>4, ks = wi&15); covers all 4 nt.
// 3 x-segments (fragment-packed buffers), A fragment-packed per CTA.
// 16-way K-split partials in ds[16][32][32], tree reduce + bias, gates.
// ---------------------------------------------------------------------------
__device__ __forceinline__ void lstm_mma(
    const unsigned* Wp, int NKT,
    const unsigned* B0, int n0, const unsigned* B1, int n1,
    const unsigned* B2, int n2,
    const float* __restrict__ bias,
    float* cst, float* hF, unsigned* packA, unsigned* packB,
    int cta, int tid, float* ds, float* s_red) {

    const int wi = tid >> 5, lane = tid & 31;
    const int mt = wi >> 4, ks = wi & 15;

    float acc[4][4];
#pragma unroll
    for (int i = 0; i < 4; i++)
#pragma unroll
        for (int j = 0; j < 4; j++) acc[i][j] = 0.f;

    const uint4* A4 = (const uint4*)Wp + ((size_t)(cta * 2 + mt) * NKT) * 64;

    const unsigned* segs[3] = { B0, B1, B2 };
    const int cnts[3] = { n0, n1, n2 };
    int ktA = 0;
#pragma unroll
    for (int sgi = 0; sgi < 3; sgi++) {
        const uint4* B4 = (const uint4*)segs[sgi];
        for (int kl = ks; kl < cnts[sgi]; kl += 16) {
            uint4 Ah = A4[(size_t)(ktA + kl) * 64 + lane * 2];
            uint4 Al = A4[(size_t)(ktA + kl) * 64 + lane * 2 + 1];
#pragma unroll
            for (int nt = 0; nt < 4; nt++) {
                uint4 Bv = B4[(size_t)(kl * 4 + nt) * 32 + lane];
                mma_bf(acc[nt], Ah.x, Ah.y, Ah.z, Ah.w, Bv.x, Bv.y);  // hi*hi
                mma_bf(acc[nt], Ah.x, Ah.y, Ah.z, Ah.w, Bv.z, Bv.w);  // hi*lo
                mma_bf(acc[nt], Al.x, Al.y, Al.z, Al.w, Bv.x, Bv.y);  // lo*hi
            }
        }
        ktA += cnts[sgi];
    }

    // partial store: D rows {mt*16+g, +8}, cols {nt*8+2t4, +1}
    __syncthreads();            // ds free from previous phase use
    {
        int g = lane >> 2, t4 = lane & 3;
        int r0 = mt * 16 + g;
#pragma unroll
        for (int nt = 0; nt < 4; nt++) {
            int c0 = nt * 8 + t4 * 2;
            ds[(ks * 32 + r0) * 32 + c0]         = acc[nt][0];
            ds[(ks * 32 + r0) * 32 + c0 + 1]     = acc[nt][1];
            ds[(ks * 32 + r0 + 8) * 32 + c0]     = acc[nt][2];
            ds[(ks * 32 + r0 + 8) * 32 + c0 + 1] = acc[nt][3];
        }
    }
    __syncthreads();
    {
        int r = tid >> 5, b = tid & 31;
        float s = bias[(r >> 3) * 1024 + cta * 8 + (r & 7)];
#pragma unroll
        for (int k2 = 0; k2 < 16; k2++) s += ds[(k2 * 32 + r) * 32 + b];
        s_red[r * 32 + b] = s;
    }
    __syncthreads();
    if (tid < 256) {
        int uoff = tid >> 5, b = tid & 31;
        int u = cta * 8 + uoff;
        float gi = s_red[(uoff) * 32 + b];
        float gf = s_red[(8 + uoff) * 32 + b];
        float gg = s_red[(16 + uoff) * 32 + b];
        float go = s_red[(24 + uoff) * 32 + b];
        float c  = cst[u * 32 + b];
        float c2 = fsig(gf) * c + fsig(gi) * ftanh(gg);
        float h2 = fsig(go) * ftanh(c2);
        cst[u * 32 + b] = c2;
        hF[(size_t)b * 1024 + u] = h2;
        pack_x(packA, u >> 4, u & 15, b, h2);
        if (packB) pack_x(packB, u >> 4, u & 15, b, h2);
    }
}

// ---------------------------------------------------------------------------
// the persistent kernel
// ---------------------------------------------------------------------------
__global__ void __launch_bounds__(NTHR, 1) k_main(
    const float* __restrict__ memory, const float* __restrict__ dec_in,
    const int*   __restrict__ memlen,
    const float* __restrict__ prenet_w1, const float* __restrict__ prenet_w2,
    const float* __restrict__ att_wih, const float* __restrict__ att_whh,
    const float* __restrict__ att_b,
    const float* __restrict__ wq, const float* __restrict__ wm,
    const float* __restrict__ v,
    const float* __restrict__ loc_conv, const float* __restrict__ loc_dense,
    const float* __restrict__ dec_wih, const float* __restrict__ dec_whh,
    const float* __restrict__ dec_b,
    const float* __restrict__ proj_w, const float* __restrict__ proj_b,
    const float* __restrict__ gate_w, const float* __restrict__ gate_b,
    float* __restrict__ out) {

    extern __shared__ __align__(16) float ds[];   // 16384 floats
    __shared__ __align__(16) float s_red[1024];
    __shared__ float s_lc[1984];

    const int cta = blockIdx.x;
    const int tid = threadIdx.x;
    const int wi = tid >> 5, lane = tid & 31;
    unsigned gen = 0;

    for (int i = tid; i < 1984; i += NTHR) s_lc[i] = loc_conv[i];

    // ---- zero recurrent state + packed x buffers ----
    for (int i = cta * NTHR + tid; i < 1024 * B; i += NBLK * NTHR) {
        g_ac[i] = 0.f; g_dc[i] = 0.f;
        g_ahF[i] = 0.f; g_dhF[i] = 0.f;
    }
    for (int i = cta * NTHR + tid; i < 512 * B; i += NBLK * NTHR) g_ctxF[i] = 0.f;
    for (int i = cta * NTHR + tid; i < B * TIN; i += NBLK * NTHR) { g_aw[i] = 0.f; g_awc[i] = 0.f; }
    for (int i = cta * NTHR + tid; i < 64 * 512; i += NBLK * NTHR) {
        g_attAh[0][i] = 0u; g_attAh[1][i] = 0u;
        g_decAh[i] = 0u;
        g_decDh[0][i] = 0u; g_decDh[1][i] = 0u;
    }
    for (int i = cta * NTHR + tid; i < 32 * 512; i += NBLK * NTHR) {
        g_attCtx[i] = 0u; g_decCtx[i] = 0u;
    }

    // ---- pack weights (own slice) ----
    prep_W(g_attW, att_wih, att_whh, NKT_ATT, 768, cta, tid);
    prep_W(g_decW, dec_wih, dec_whh, NKT_DEC, 1536, cta, tid);

    // ---- prenet for all 512 steps (32 rounds x 4 groups of 256 threads) ----
    {
        int grp = tid >> 8, sub = tid & 255;
        float* sd = ds + grp * 512;
        float* sx = sd + 96;
        for (int r = 0; r < 32; r++) {
            int job = r * 512 + cta * 4 + grp;
            int t = job >> 5, b = job & 31;
            __syncthreads();
            if (sub < 80)
                sd[sub] = (t == 0) ? 0.f : dec_in[(size_t)b * NMEL * TOUT + sub * TOUT + (t - 1)];
            __syncthreads();
            float s = 0.f;
            const float* w = prenet_w1 + sub * 80;
#pragma unroll 8
            for (int m = 0; m < 80; m++) s += w[m] * sd[m];
            sx[sub] = fmaxf(s, 0.f);
            __syncthreads();
            s = 0.f;
            const float* w2 = prenet_w2 + sub * 256;
#pragma unroll 8
            for (int m = 0; m < 256; m++) s += w2[m] * sx[m];
            s = fmaxf(s, 0.f);
            pack_x(g_attP + (size_t)t * 8192, sub >> 4, sub & 15, b, s);
        }
    }

    // ---- processed_memory + memory transpose (8 rounds x 8 groups of 128) ----
    {
        int grp = tid >> 7, sub = tid & 127;
        float* sm = ds + 8192 + grp * 512;
        for (int r = 0; r < 8; r++) {
            int job = r * 1024 + cta * 8 + grp;
            int tt = job >> 5, b = job & 31;
            __syncthreads();
            for (int e = sub; e < 512; e += 128) {
                float vv = memory[((size_t)b * TIN + tt) * 512 + e];
                sm[e] = vv;
                g_memT[((size_t)b * 512 + e) * TIN + tt] = vv;
            }
            __syncthreads();
            float s = 0.f;
            const float* w = wm + sub * 512;
#pragma unroll 8
            for (int e = 0; e < 512; e++) s += w[e] * sm[e];
            g_pm[((size_t)b * 128 + sub) * TIN + tt] = s;
        }
    }

    gbar(gen);

    // ======================= main recurrence =======================
    for (int t = 0; t < TOUT; t++) {
        int p = t & 1;

        // ---- P1: attention LSTM (MMA) ----
        lstm_mma(g_attW, NKT_ATT,
                 g_attP + (size_t)t * 8192, 16,
                 g_attCtx, 32,
                 g_attAh[p], 64,
                 att_b, g_ac, g_ahF, g_attAh[p ^ 1], g_decAh,
                 cta, tid, ds, s_red);
        gbar(gen);

        // ---- P2: pq = ah @ wq^T (all CTAs; a = cta, warp = batch) ----
        {
            int b = wi;
            float s = 0.f;
            const float* wr = wq + (size_t)cta * 1024;
            const float* hv = g_ahF + (size_t)b * 1024;
#pragma unroll 8
            for (int j = 0; j < 32; j++) {
                int f = lane + 32 * j;
                s += wr[f] * hv[f];
            }
#pragma unroll
            for (int o = 16; o; o >>= 1) s += __shfl_down_sync(0xffffffffu, s, o);
            if (lane == 0) g_pq[b * 128 + cta] = s;
        }
        gbar(gen);

        // ---- P3: energies (2 tiles per CTA, 512 threads each) ----
        {
            int ts = tid >> 9, sub = tid & 511;
            int tile = cta * 2 + ts;            // (b, t-tile)
            int b = tile >> 3;
            int t0 = (tile & 7) * 32;
            float* scr  = ds + ts * 2048;
            float* cat  = scr;                  // [2][64]
            float* co   = scr + 128;            // [32][33]
            float* spq  = scr + 1184;           // [128]
            float* part = scr + 1312;           // [16][32]
            if (sub < 124) {
                int c = sub / 62, tl = sub % 62;
                int tg = t0 - 15 + tl;
                float vv = 0.f;
                if (tg >= 0 && tg < TIN) vv = (c ? g_awc : g_aw)[b * TIN + tg];
                cat[c * 64 + tl] = vv;
            }
            if (sub < 128) spq[sub] = g_pq[b * 128 + sub];
            __syncthreads();
#pragma unroll
            for (int j = 0; j < 2; j++) {
                int id = sub + j * 512;
                int tl = id >> 5, f = id & 31;
                const float* lc = &s_lc[f * 62];
                float s = 0.f;
#pragma unroll
                for (int k = 0; k < 31; k++) s += lc[k] * cat[tl + k];
#pragma unroll
                for (int k = 0; k < 31; k++) s += lc[31 + k] * cat[64 + tl + k];
                co[tl * 33 + f] = s;
            }
            __syncthreads();
            {
                int wa = sub >> 5, tl = sub & 31;
                const float* corow = co + tl * 33;
                const float* pmb = g_pm + ((size_t)b * 128) * TIN + t0 + tl;
                float acc = 0.f;
#pragma unroll 2
                for (int a = wa * 8; a < wa * 8 + 8; a++) {
                    const float* dw = loc_dense + a * 32;
                    float loc = 0.f;
#pragma unroll
                    for (int f = 0; f < 32; f++) loc += __ldg(dw + f) * corow[f];
                    float pmv = pmb[(size_t)a * TIN];
                    acc += ftanh(spq[a] + pmv + loc) * __ldg(v + a);
                }
                part[wa * 32 + tl] = acc;
            }
            __syncthreads();
            if (sub < 32) {
                float e = 0.f;
#pragma unroll
                for (int j = 0; j < 16; j++) e += part[j * 32 + sub];
                int tg = t0 + sub;
                if (tg >= memlen[b]) e = -1e9f;
                g_e[b * TIN + tg] = e;
            }
        }
        gbar(gen);

        // ---- P4: softmax + context (CTA -> (b, e-quarter)) ----
        {
            int b = cta >> 2, x = cta & 3;
            float* s_wgt = ds;
            float* red   = ds + 256;
            float* bval  = ds + 266;
            float e = (tid < 256) ? g_e[b * 256 + tid] : -1e30f;
            float m = e;
#pragma unroll
            for (int o = 16; o; o >>= 1) m = fmaxf(m, __shfl_xor_sync(0xffffffffu, m, o));
            if (lane == 0 && tid < 256) red[wi] = m;
            __syncthreads();
            if (tid == 0) {
                float mm = red[0];
#pragma unroll
                for (int i = 1; i < 8; i++) mm = fmaxf(mm, red[i]);
                bval[0] = mm;
            }
            __syncthreads();
            float w0 = (tid < 256) ? __expf(e - bval[0]) : 0.f;
            float ssum = w0;
#pragma unroll
            for (int o = 16; o; o >>= 1) ssum += __shfl_xor_sync(0xffffffffu, ssum, o);
            if (lane == 0 && tid < 256) red[wi] = ssum;
            __syncthreads();
            if (tid == 0) {
                float tt2 = 0.f;
#pragma unroll
                for (int i = 0; i < 8; i++) tt2 += red[i];
                bval[1] = tt2;
            }
            __syncthreads();
            if (tid < 256) {
                float wgt = w0 * __fdividef(1.f, bval[1]);
                s_wgt[tid] = wgt;
                if (x == 0) {
                    g_aw[b * 256 + tid] = wgt;
                    g_awc[b * 256 + tid] += wgt;
                    out[ALIGN_OFF + (size_t)(b * TOUT + t) * TIN + tid] = wgt;
                }
            }
            __syncthreads();
            {
                int ebase = x * 128 + wi * 4;
#pragma unroll
                for (int i = 0; i < 4; i++) {
                    int e2 = ebase + i;
                    const float* mrow = g_memT + ((size_t)b * 512 + e2) * TIN;
                    float s = 0.f;
#pragma unroll
                    for (int j = 0; j < 8; j++) {
                        int tt3 = lane + 32 * j;
                        s += mrow[tt3] * s_wgt[tt3];
                    }
#pragma unroll
                    for (int o = 16; o; o >>= 1) s += __shfl_down_sync(0xffffffffu, s, o);
                    if (lane == 0) {
                        g_ctxF[(size_t)b * 512 + e2] = s;
                        pack_x(g_attCtx, e2 >> 4, e2 & 15, b, s);
                        pack_x(g_decCtx, e2 >> 4, e2 & 15, b, s);
                    }
                }
            }
        }
        gbar(gen);

        // ---- P5: decoder LSTM (MMA) ----
        lstm_mma(g_decW, NKT_DEC,
                 g_decAh, 64,
                 g_decCtx, 32,
                 g_decDh[p], 64,
                 dec_b, g_dc, g_dhF, g_decDh[p ^ 1], (unsigned*)0,
                 cta, tid, ds, s_red);
        gbar(gen);

        // ---- P6: projection + gate (CTAs 0..80; o = cta, warp = batch) ----
        if (cta < 81) {
            int b = wi;
            float s = 0.f;
            const float* wrow = (cta < 80) ? (proj_w + (size_t)cta * 1536) : gate_w;
            const float* dv = g_dhF + (size_t)b * 1024;
            const float* cv = g_ctxF + (size_t)b * 512;
#pragma unroll 8
            for (int j = 0; j < 48; j++) {
                int f = lane + 32 * j;
                float xv = (f < 1024) ? dv[f] : cv[f - 1024];
                s += wrow[f] * xv;
            }
#pragma unroll
            for (int o = 16; o; o >>= 1) s += __shfl_down_sync(0xffffffffu, s, o);
            if (lane == 0) {
                if (cta < 80)
                    out[((size_t)b * NMEL + cta) * TOUT + t] = s + proj_b[cta];
                else
                    out[GATE_OFF + (size_t)b * TOUT + t] = s + gate_b[0];
            }
        }
    }
}

// ---------------------------------------------------------------------------
// launch: 2 graph nodes
// ---------------------------------------------------------------------------
extern "C" void kernel_launch(void* const* d_in, const int* in_sizes, int n_in,
                              void* d_out, int out_size) {
    const float* memory    = (const float*)d_in[0];
    const float* dec_in    = (const float*)d_in[1];
    const int*   memlen    = (const int*)  d_in[2];
    const float* prenet_w1 = (const float*)d_in[3];
    const float* prenet_w2 = (const float*)d_in[4];
    const float* att_wih   = (const float*)d_in[5];
    const float* att_whh   = (const float*)d_in[6];
    const float* att_b     = (const float*)d_in[7];
    const float* wq        = (const float*)d_in[8];
    const float* wm        = (const float*)d_in[9];
    const float* v         = (const float*)d_in[10];
    const float* loc_conv  = (const float*)d_in[11];
    const float* loc_dense = (const float*)d_in[12];
    const float* dec_wih   = (const float*)d_in[13];
    const float* dec_whh   = (const float*)d_in[14];
    const float* dec_b     = (const float*)d_in[15];
    const float* proj_w    = (const float*)d_in[16];
    const float* proj_b    = (const float*)d_in[17];
    const float* gate_w    = (const float*)d_in[18];
    const float* gate_b    = (const float*)d_in[19];
    float* out = (float*)d_out;

    cudaFuncSetAttribute(k_main, cudaFuncAttributeMaxDynamicSharedMemorySize, DSBYTES);

    k_reset<<<1, 32>>>();
    k_main<<<NBLK, NTHR, DSBYTES>>>(memory, dec_in, memlen, prenet_w1, prenet_w2,
                                    att_wih, att_whh, att_b, wq, wm, v,
                                    loc_conv, loc_dense, dec_wih, dec_whh, dec_b,
                                    proj_w, proj_b, gate_w, gate_b, out);
}